// round 1
// baseline (speedup 1.0000x reference)
#include <cuda_runtime.h>
#include <cuda_bf16.h>
#include <cstdint>

// Problem constants
#define BATCH 4
#define TT 8
#define HH 64
#define WW 64
#define CC 256
#define NTOK (BATCH*TT*HH*WW)          // 131072 tokens
#define NHEAD 8
#define HD 32
#define NWIN 1024                      // B * (T/2)*(H/8)*(W/8) = 4*256
#define NTOKW 128                      // tokens per window
#define QKV_N 768
#define HID 512
#define SCALE 0.17677669529663687f     // 1/sqrt(32)

// ---------------- scratch (static device globals; no runtime alloc) ----------------
__device__ float g_xn [NTOK * CC];     // LN output
__device__ float g_qkv[NTOK * QKV_N];  // fused qkv
__device__ float g_att[NTOK * CC];     // attention output (pre-proj)
__device__ float g_hid[NTOK * HID];    // mlp hidden
__device__ float g_x  [NTOK * CC];     // running residual state

// ---------------- LayerNorm: one warp per token ----------------
__global__ __launch_bounds__(256)
void ln_kernel(const float* __restrict__ x, const float* __restrict__ g,
               const float* __restrict__ b, float* __restrict__ out)
{
    int gw   = (blockIdx.x * blockDim.x + threadIdx.x) >> 5;
    int lane = threadIdx.x & 31;
    if (gw >= NTOK) return;
    const float4* row = (const float4*)(x + (size_t)gw * CC);
    float4 v0 = row[lane];
    float4 v1 = row[lane + 32];
    float s = v0.x+v0.y+v0.z+v0.w + v1.x+v1.y+v1.z+v1.w;
    float q = v0.x*v0.x+v0.y*v0.y+v0.z*v0.z+v0.w*v0.w
            + v1.x*v1.x+v1.y*v1.y+v1.z*v1.z+v1.w*v1.w;
    #pragma unroll
    for (int o = 16; o > 0; o >>= 1) {
        s += __shfl_xor_sync(0xffffffffu, s, o);
        q += __shfl_xor_sync(0xffffffffu, q, o);
    }
    float mean = s * (1.0f/256.0f);
    float var  = q * (1.0f/256.0f) - mean*mean;
    float rstd = rsqrtf(var + 1e-5f);
    const float4* g4 = (const float4*)g;
    const float4* b4 = (const float4*)b;
    float4 ga = g4[lane], gb2 = g4[lane+32];
    float4 ba = b4[lane], bb2 = b4[lane+32];
    float4 o0, o1;
    o0.x = (v0.x-mean)*rstd*ga.x  + ba.x;
    o0.y = (v0.y-mean)*rstd*ga.y  + ba.y;
    o0.z = (v0.z-mean)*rstd*ga.z  + ba.z;
    o0.w = (v0.w-mean)*rstd*ga.w  + ba.w;
    o1.x = (v1.x-mean)*rstd*gb2.x + bb2.x;
    o1.y = (v1.y-mean)*rstd*gb2.y + bb2.y;
    o1.z = (v1.z-mean)*rstd*gb2.z + bb2.z;
    o1.w = (v1.w-mean)*rstd*gb2.w + bb2.w;
    float4* orow = (float4*)(out + (size_t)gw * CC);
    orow[lane]      = o0;
    orow[lane + 32] = o1;
}

// ---------------- SGEMM 128x128x8, 256 threads, 8x8/thread, double-buffered ----------------
// EPI: 0 = bias only, 1 = bias + exact GELU, 2 = bias + residual add
__device__ __forceinline__ float gelu_exact(float x) {
    return 0.5f * x * (1.0f + erff(x * 0.7071067811865475f));
}

template<int EPI>
__global__ __launch_bounds__(256, 2)
void sgemm_kernel(int M, int N, int K,
                  const float* __restrict__ A,
                  const float* __restrict__ B,
                  const float* __restrict__ bias,
                  const float* __restrict__ Res,
                  float* __restrict__ C)
{
    const int BM = 128, BN = 128, BK = 8;
    __shared__ float As[2][BK][BM];
    __shared__ float Bs[2][BK][BN];

    int tid = threadIdx.x;
    int bm  = blockIdx.y;
    int bn  = blockIdx.x;

    const float* Ab = A + (size_t)bm * BM * K;
    const float* Bb = B + (size_t)bn * BN;

    int a_r = tid >> 1,  a_c = (tid & 1) * 4;    // 128 rows x 8 cols, float4 per thread
    int b_r = tid >> 5,  b_c = (tid & 31) * 4;   // 8 rows x 128 cols
    int tx  = tid & 15,  ty  = tid >> 4;

    float acc[8][8];
    #pragma unroll
    for (int i = 0; i < 8; i++)
        #pragma unroll
        for (int j = 0; j < 8; j++) acc[i][j] = 0.0f;

    // prefetch tile 0
    float4 a4 = *(const float4*)(Ab + (size_t)a_r * K + a_c);
    float4 b4 = *(const float4*)(Bb + (size_t)b_r * N + b_c);
    As[0][a_c+0][a_r] = a4.x;
    As[0][a_c+1][a_r] = a4.y;
    As[0][a_c+2][a_r] = a4.z;
    As[0][a_c+3][a_r] = a4.w;
    *(float4*)&Bs[0][b_r][b_c] = b4;
    __syncthreads();

    int nk  = K >> 3;
    int buf = 0;
    for (int kt = 0; kt < nk; ++kt) {
        float4 a4n, b4n;
        if (kt + 1 < nk) {
            a4n = *(const float4*)(Ab + (size_t)a_r * K + (kt+1)*BK + a_c);
            b4n = *(const float4*)(Bb + (size_t)((kt+1)*BK + b_r) * N + b_c);
        }
        #pragma unroll
        for (int k = 0; k < BK; ++k) {
            float ar[8], br[8];
            *(float4*)(ar)   = *(const float4*)&As[buf][k][ty*8];
            *(float4*)(ar+4) = *(const float4*)&As[buf][k][ty*8+4];
            *(float4*)(br)   = *(const float4*)&Bs[buf][k][tx*8];
            *(float4*)(br+4) = *(const float4*)&Bs[buf][k][tx*8+4];
            #pragma unroll
            for (int i = 0; i < 8; i++)
                #pragma unroll
                for (int j = 0; j < 8; j++)
                    acc[i][j] += ar[i] * br[j];
        }
        if (kt + 1 < nk) {
            buf ^= 1;
            As[buf][a_c+0][a_r] = a4n.x;
            As[buf][a_c+1][a_r] = a4n.y;
            As[buf][a_c+2][a_r] = a4n.z;
            As[buf][a_c+3][a_r] = a4n.w;
            *(float4*)&Bs[buf][b_r][b_c] = b4n;
            __syncthreads();
        }
    }

    int row0 = bm * BM + ty * 8;
    int col0 = bn * BN + tx * 8;
    float4 bi0 = *(const float4*)(bias + col0);
    float4 bi1 = *(const float4*)(bias + col0 + 4);
    #pragma unroll
    for (int i = 0; i < 8; i++) {
        size_t off = (size_t)(row0 + i) * N + col0;
        float4 c0, c1;
        c0.x = acc[i][0] + bi0.x;  c0.y = acc[i][1] + bi0.y;
        c0.z = acc[i][2] + bi0.z;  c0.w = acc[i][3] + bi0.w;
        c1.x = acc[i][4] + bi1.x;  c1.y = acc[i][5] + bi1.y;
        c1.z = acc[i][6] + bi1.z;  c1.w = acc[i][7] + bi1.w;
        if (EPI == 1) {
            c0.x = gelu_exact(c0.x); c0.y = gelu_exact(c0.y);
            c0.z = gelu_exact(c0.z); c0.w = gelu_exact(c0.w);
            c1.x = gelu_exact(c1.x); c1.y = gelu_exact(c1.y);
            c1.z = gelu_exact(c1.z); c1.w = gelu_exact(c1.w);
        }
        if (EPI == 2) {
            float4 r0 = *(const float4*)(Res + off);
            float4 r1 = *(const float4*)(Res + off + 4);
            c0.x += r0.x; c0.y += r0.y; c0.z += r0.z; c0.w += r0.w;
            c1.x += r1.x; c1.y += r1.y; c1.z += r1.z; c1.w += r1.w;
        }
        *(float4*)(C + off)     = c0;
        *(float4*)(C + off + 4) = c1;
    }
}

// ---------------- Windowed attention: one CTA per (window, head) ----------------
// Token layout stays flat [B*T*H*W, C]; window partition / shift / reverse are
// pure index math. Relative-position-bias index and shift-mask labels computed
// on the fly.
template<bool SHIFT>
__global__ __launch_bounds__(128)
void attn_kernel(const float* __restrict__ qkv,
                 const float* __restrict__ rpb,
                 float* __restrict__ out)
{
    extern __shared__ float sm[];
    float* sk = sm;                      // [128][32]
    float* sv = sk + 128*32;             // [128][32]
    float* sp = sv + 128*32;             // [128][129] scores (pitch 129: conflict-free)
    int*   slab = (int*)(sp + 128*129);  // [128] region labels (SHIFT only)

    int n    = threadIdx.x;              // token within window
    int head = blockIdx.y;
    int win  = blockIdx.x;
    int b  = win >> 8;
    int r  = win & 255;
    int wt = r >> 6, wh = (r >> 3) & 7, wwi = r & 7;
    int ti = n >> 6, hi = (n >> 3) & 7, wi  = n & 7;
    // position in (possibly shifted) space
    int pt = wt*2 + ti, ph = wh*8 + hi, pw = wwi*8 + wi;
    int t, h, w;
    if (SHIFT) { t = (pt + 1) & 7; h = (ph + 4) & 63; w = (pw + 4) & 63; }
    else       { t = pt;           h = ph;            w = pw; }
    int tok = ((b*TT + t)*HH + h)*WW + w;

    int mylab = 0;
    if (SHIFT) {
        int lt = pt < 6  ? 0 : (pt < 7  ? 1 : 2);
        int lh = ph < 56 ? 0 : (ph < 60 ? 1 : 2);
        int lw = pw < 56 ? 0 : (pw < 60 ? 1 : 2);
        mylab = lt*9 + lh*3 + lw;
        slab[n] = mylab;
    }

    // load q row into registers (scaled), k/v rows into smem
    const float* qp = qkv + (size_t)tok * QKV_N + head * HD;
    float qr[32];
    #pragma unroll
    for (int i = 0; i < 8; i++) {
        float4 qv = ((const float4*)qp)[i];
        qr[4*i+0] = qv.x * SCALE; qr[4*i+1] = qv.y * SCALE;
        qr[4*i+2] = qv.z * SCALE; qr[4*i+3] = qv.w * SCALE;
        float4 kv = ((const float4*)(qp + CC))[i];
        *(float4*)(sk + n*32 + 4*i) = kv;
        float4 vv = ((const float4*)(qp + 2*CC))[i];
        *(float4*)(sv + n*32 + 4*i) = vv;
    }
    __syncthreads();

    float* myrow = sp + n * 129;
    float mx = -1e30f;
    #pragma unroll 2
    for (int j = 0; j < 128; j++) {
        int tj = j >> 6, hj = (j >> 3) & 7, wj = j & 7;
        const float4* kr = (const float4*)(sk + j*32);
        float s0 = 0.f, s1 = 0.f, s2 = 0.f, s3 = 0.f;
        #pragma unroll
        for (int d = 0; d < 8; d++) {
            float4 kv = kr[d];
            s0 += qr[4*d+0] * kv.x;
            s1 += qr[4*d+1] * kv.y;
            s2 += qr[4*d+2] * kv.z;
            s3 += qr[4*d+3] * kv.w;
        }
        int rel = (ti - tj + 1)*225 + (hi - hj + 7)*15 + (wi - wj + 7);
        float s = (s0 + s1) + (s2 + s3) + __ldg(rpb + rel*NHEAD + head);
        if (SHIFT && slab[j] != mylab) s -= 100.0f;
        myrow[j] = s;
        mx = fmaxf(mx, s);
    }
    float sum = 0.f;
    #pragma unroll 4
    for (int j = 0; j < 128; j++) {
        float e = __expf(myrow[j] - mx);
        myrow[j] = e;
        sum += e;
    }
    float inv = 1.0f / sum;

    float o[32];
    #pragma unroll
    for (int d = 0; d < 32; d++) o[d] = 0.f;
    #pragma unroll 2
    for (int j = 0; j < 128; j++) {
        float p = myrow[j];
        const float4* vr = (const float4*)(sv + j*32);
        #pragma unroll
        for (int d = 0; d < 8; d++) {
            float4 vv = vr[d];
            o[4*d+0] += p * vv.x;
            o[4*d+1] += p * vv.y;
            o[4*d+2] += p * vv.z;
            o[4*d+3] += p * vv.w;
        }
    }
    float* op = out + (size_t)tok * CC + head * HD;
    #pragma unroll
    for (int i = 0; i < 8; i++) {
        float4 ov;
        ov.x = o[4*i+0]*inv; ov.y = o[4*i+1]*inv;
        ov.z = o[4*i+2]*inv; ov.w = o[4*i+3]*inv;
        ((float4*)op)[i] = ov;
    }
}

// ---------------- host orchestration ----------------
#define ATTN_SMEM ((2*128*32 + 128*129)*4 + 128*4)

extern "C" void kernel_launch(void* const* d_in, const int* in_sizes, int n_in,
                              void* d_out, int out_size)
{
    const float* x       = (const float*)d_in[0];
    const float* rpb1    = (const float*)d_in[1];
    const float* qkv_w1  = (const float*)d_in[2];
    const float* qkv_b1  = (const float*)d_in[3];
    const float* proj_w1 = (const float*)d_in[4];
    const float* proj_b1 = (const float*)d_in[5];
    const float* rpb2    = (const float*)d_in[6];
    const float* qkv_w2  = (const float*)d_in[7];
    const float* qkv_b2  = (const float*)d_in[8];
    const float* proj_w2 = (const float*)d_in[9];
    const float* proj_b2 = (const float*)d_in[10];
    const float* g1  = (const float*)d_in[11];
    const float* be1 = (const float*)d_in[12];
    const float* g2  = (const float*)d_in[13];
    const float* be2 = (const float*)d_in[14];
    const float* g3  = (const float*)d_in[15];
    const float* be3 = (const float*)d_in[16];
    const float* g4  = (const float*)d_in[17];
    const float* be4 = (const float*)d_in[18];
    const float* m1w1 = (const float*)d_in[19];
    const float* m1b1 = (const float*)d_in[20];
    const float* m1w2 = (const float*)d_in[21];
    const float* m1b2 = (const float*)d_in[22];
    const float* m2w1 = (const float*)d_in[23];
    const float* m2b1 = (const float*)d_in[24];
    const float* m2w2 = (const float*)d_in[25];
    const float* m2b2 = (const float*)d_in[26];
    float* out = (float*)d_out;

    float *xn, *qkvb, *att, *hid, *xb;
    cudaGetSymbolAddress((void**)&xn,   g_xn);
    cudaGetSymbolAddress((void**)&qkvb, g_qkv);
    cudaGetSymbolAddress((void**)&att,  g_att);
    cudaGetSymbolAddress((void**)&hid,  g_hid);
    cudaGetSymbolAddress((void**)&xb,   g_x);

    cudaFuncSetAttribute(attn_kernel<false>,
        cudaFuncAttributeMaxDynamicSharedMemorySize, ATTN_SMEM);
    cudaFuncSetAttribute(attn_kernel<true>,
        cudaFuncAttributeMaxDynamicSharedMemorySize, ATTN_SMEM);

    const int M = NTOK;
    dim3 lnGrid(M / 8);              // warp per token, 8 warps per 256-thread block
    dim3 attnGrid(NWIN, NHEAD);

    // ---- block 1: window attention (no shift) ----
    ln_kernel<<<lnGrid, 256>>>(x, g1, be1, xn);
    sgemm_kernel<0><<<dim3(QKV_N/128, M/128), 256>>>(M, QKV_N, CC, xn, qkv_w1, qkv_b1, nullptr, qkvb);
    attn_kernel<false><<<attnGrid, 128, ATTN_SMEM>>>(qkvb, rpb1, att);
    sgemm_kernel<2><<<dim3(CC/128, M/128), 256>>>(M, CC, CC, att, proj_w1, proj_b1, x, xb);
    // mlp 1
    ln_kernel<<<lnGrid, 256>>>(xb, g2, be2, xn);
    sgemm_kernel<1><<<dim3(HID/128, M/128), 256>>>(M, HID, CC, xn, m1w1, m1b1, nullptr, hid);
    sgemm_kernel<2><<<dim3(CC/128, M/128), 256>>>(M, CC, HID, hid, m1w2, m1b2, xb, xb);

    // ---- block 2: shifted window attention with mask ----
    ln_kernel<<<lnGrid, 256>>>(xb, g3, be3, xn);
    sgemm_kernel<0><<<dim3(QKV_N/128, M/128), 256>>>(M, QKV_N, CC, xn, qkv_w2, qkv_b2, nullptr, qkvb);
    attn_kernel<true><<<attnGrid, 128, ATTN_SMEM>>>(qkvb, rpb2, att);
    sgemm_kernel<2><<<dim3(CC/128, M/128), 256>>>(M, CC, CC, att, proj_w2, proj_b2, xb, xb);
    // mlp 2 (final GEMM writes straight to d_out with residual)
    ln_kernel<<<lnGrid, 256>>>(xb, g4, be4, xn);
    sgemm_kernel<1><<<dim3(HID/128, M/128), 256>>>(M, HID, CC, xn, m2w1, m2b1, nullptr, hid);
    sgemm_kernel<2><<<dim3(CC/128, M/128), 256>>>(M, CC, HID, hid, m2w2, m2b2, xb, out);
}

// round 2
// speedup vs baseline: 1.4922x; 1.4922x over previous
#include <cuda_runtime.h>
#include <cuda_bf16.h>
#include <cstdint>

// Problem constants
#define BATCH 4
#define TT 8
#define HH 64
#define WW 64
#define CC 256
#define NTOK (BATCH*TT*HH*WW)          // 131072 tokens
#define NHEAD 8
#define HD 32
#define NWIN 1024
#define QKV_N 768
#define HID 512
#define SCALE 0.17677669529663687f     // 1/sqrt(32)

// ---------------- scratch ----------------
__device__ float g_xn [NTOK * CC];
__device__ float g_qkv[NTOK * QKV_N];
__device__ float g_att[NTOK * CC];
__device__ float g_hid[NTOK * HID];
__device__ float g_x  [NTOK * CC];

// ---------------- LayerNorm: one warp per token ----------------
__global__ __launch_bounds__(256)
void ln_kernel(const float* __restrict__ x, const float* __restrict__ g,
               const float* __restrict__ b, float* __restrict__ out)
{
    int gw   = (blockIdx.x * blockDim.x + threadIdx.x) >> 5;
    int lane = threadIdx.x & 31;
    if (gw >= NTOK) return;
    const float4* row = (const float4*)(x + (size_t)gw * CC);
    float4 v0 = row[lane];
    float4 v1 = row[lane + 32];
    float s = v0.x+v0.y+v0.z+v0.w + v1.x+v1.y+v1.z+v1.w;
    float q = v0.x*v0.x+v0.y*v0.y+v0.z*v0.z+v0.w*v0.w
            + v1.x*v1.x+v1.y*v1.y+v1.z*v1.z+v1.w*v1.w;
    #pragma unroll
    for (int o = 16; o > 0; o >>= 1) {
        s += __shfl_xor_sync(0xffffffffu, s, o);
        q += __shfl_xor_sync(0xffffffffu, q, o);
    }
    float mean = s * (1.0f/256.0f);
    float var  = q * (1.0f/256.0f) - mean*mean;
    float rstd = rsqrtf(var + 1e-5f);
    const float4* g4 = (const float4*)g;
    const float4* b4 = (const float4*)b;
    float4 ga = g4[lane], gb2 = g4[lane+32];
    float4 ba = b4[lane], bb2 = b4[lane+32];
    float4 o0, o1;
    o0.x = (v0.x-mean)*rstd*ga.x  + ba.x;
    o0.y = (v0.y-mean)*rstd*ga.y  + ba.y;
    o0.z = (v0.z-mean)*rstd*ga.z  + ba.z;
    o0.w = (v0.w-mean)*rstd*ga.w  + ba.w;
    o1.x = (v1.x-mean)*rstd*gb2.x + bb2.x;
    o1.y = (v1.y-mean)*rstd*gb2.y + bb2.y;
    o1.z = (v1.z-mean)*rstd*gb2.z + bb2.z;
    o1.w = (v1.w-mean)*rstd*gb2.w + bb2.w;
    float4* orow = (float4*)(out + (size_t)gw * CC);
    orow[lane]      = o0;
    orow[lane + 32] = o1;
}

// ---------------- bf16x3 tensor-core GEMM ----------------
// C[M,N] = A[M,K] @ B[K,N] + bias (+gelu | +residual), fp32 in/out.
// A,B split into bf16 hi+lo during smem store; 3 MMA passes: hh + hl + lh.
#define BM 128
#define BN 64
#define BKF 32
#define APAD 40
#define BPAD 72
#define GSMEM_BYTES ((2*2*BM*APAD + 2*2*BKF*BPAD) * 2)

__device__ __forceinline__ float gelu_exact(float x) {
    return 0.5f * x * (1.0f + erff(x * 0.7071067811865475f));
}

__device__ __forceinline__ void ldsm_x4(uint32_t* r, const __nv_bfloat16* p) {
    uint32_t a = (uint32_t)__cvta_generic_to_shared(p);
    asm volatile("ldmatrix.sync.aligned.m8n8.x4.shared.b16 {%0,%1,%2,%3}, [%4];"
        : "=r"(r[0]), "=r"(r[1]), "=r"(r[2]), "=r"(r[3]) : "r"(a));
}
__device__ __forceinline__ void ldsm_x4t(uint32_t* r, const __nv_bfloat16* p) {
    uint32_t a = (uint32_t)__cvta_generic_to_shared(p);
    asm volatile("ldmatrix.sync.aligned.m8n8.x4.trans.shared.b16 {%0,%1,%2,%3}, [%4];"
        : "=r"(r[0]), "=r"(r[1]), "=r"(r[2]), "=r"(r[3]) : "r"(a));
}
__device__ __forceinline__ void mma_bf16(float* c, const uint32_t* a, const uint32_t* b) {
    asm volatile(
        "mma.sync.aligned.m16n8k16.row.col.f32.bf16.bf16.f32 "
        "{%0,%1,%2,%3}, {%4,%5,%6,%7}, {%8,%9}, {%0,%1,%2,%3};"
        : "+f"(c[0]), "+f"(c[1]), "+f"(c[2]), "+f"(c[3])
        : "r"(a[0]), "r"(a[1]), "r"(a[2]), "r"(a[3]), "r"(b[0]), "r"(b[1]));
}
// split two consecutive fp32 into packed bf16 hi-pair and lo-pair
__device__ __forceinline__ void split2(float x0, float x1, uint32_t& h, uint32_t& l) {
    __nv_bfloat16 h0 = __float2bfloat16(x0);
    __nv_bfloat16 h1 = __float2bfloat16(x1);
    __nv_bfloat16 l0 = __float2bfloat16(x0 - __bfloat162float(h0));
    __nv_bfloat16 l1 = __float2bfloat16(x1 - __bfloat162float(h1));
    uint16_t uh0 = *(uint16_t*)&h0, uh1 = *(uint16_t*)&h1;
    uint16_t ul0 = *(uint16_t*)&l0, ul1 = *(uint16_t*)&l1;
    h = (uint32_t)uh0 | ((uint32_t)uh1 << 16);
    l = (uint32_t)ul0 | ((uint32_t)ul1 << 16);
}

template<int EPI>   // 0=bias, 1=bias+gelu, 2=bias+residual
__global__ __launch_bounds__(256, 2)
void hgemm_kernel(int M, int N, int K,
                  const float* __restrict__ A,
                  const float* __restrict__ B,
                  const float* __restrict__ bias,
                  const float* __restrict__ Res,
                  float* __restrict__ C)
{
    extern __shared__ __nv_bfloat16 smg[];
    __nv_bfloat16* As = smg;                        // [2][2][BM][APAD]
    __nv_bfloat16* Bs = smg + 2*2*BM*APAD;          // [2][2][BKF][BPAD]

    int tid  = threadIdx.x;
    int bm   = blockIdx.y, bn = blockIdx.x;
    int warp = tid >> 5, lane = tid & 31;
    int wm   = warp >> 1, wn = warp & 1;

    const float* Ab = A + (size_t)bm * BM * K;
    const float* Bb = B + bn * BN;

    int ar = tid >> 1, ac = (tid & 1) * 16;   // A: 128 rows x 32 cols, 16 floats/thread
    int br = tid >> 3, bc = (tid & 7) * 8;    // B: 32 rows x 64 cols, 8 floats/thread

    float acc[2][4][4];
    #pragma unroll
    for (int i = 0; i < 2; i++)
        #pragma unroll
        for (int j = 0; j < 4; j++)
            #pragma unroll
            for (int k = 0; k < 4; k++) acc[i][j][k] = 0.0f;

    float4 pa[4], pb[2];
    #pragma unroll
    for (int i = 0; i < 4; i++)
        pa[i] = *(const float4*)(Ab + (size_t)ar * K + ac + 4*i);
    #pragma unroll
    for (int i = 0; i < 2; i++)
        pb[i] = *(const float4*)(Bb + (size_t)br * N + bc + 4*i);

    // store tile 0
    {
        __nv_bfloat16* Ah = As + 0;
        __nv_bfloat16* Al = As + BM*APAD;
        __nv_bfloat16* Bh = Bs + 0;
        __nv_bfloat16* Bl = Bs + BKF*BPAD;
        #pragma unroll
        for (int i = 0; i < 4; i++) {
            uint32_t h, l;
            split2(pa[i].x, pa[i].y, h, l);
            *(uint32_t*)(Ah + ar*APAD + ac + 4*i)     = h;
            *(uint32_t*)(Al + ar*APAD + ac + 4*i)     = l;
            split2(pa[i].z, pa[i].w, h, l);
            *(uint32_t*)(Ah + ar*APAD + ac + 4*i + 2) = h;
            *(uint32_t*)(Al + ar*APAD + ac + 4*i + 2) = l;
        }
        #pragma unroll
        for (int i = 0; i < 2; i++) {
            uint32_t h, l;
            split2(pb[i].x, pb[i].y, h, l);
            *(uint32_t*)(Bh + br*BPAD + bc + 4*i)     = h;
            *(uint32_t*)(Bl + br*BPAD + bc + 4*i)     = l;
            split2(pb[i].z, pb[i].w, h, l);
            *(uint32_t*)(Bh + br*BPAD + bc + 4*i + 2) = h;
            *(uint32_t*)(Bl + br*BPAD + bc + 4*i + 2) = l;
        }
    }
    __syncthreads();

    int nk = K / BKF;
    for (int kt = 0; kt < nk; kt++) {
        if (kt + 1 < nk) {
            #pragma unroll
            for (int i = 0; i < 4; i++)
                pa[i] = *(const float4*)(Ab + (size_t)ar * K + (kt+1)*BKF + ac + 4*i);
            #pragma unroll
            for (int i = 0; i < 2; i++)
                pb[i] = *(const float4*)(Bb + (size_t)((kt+1)*BKF + br) * N + bc + 4*i);
        }
        int buf = kt & 1;
        const __nv_bfloat16* Ah = As + (buf*2+0)*BM*APAD;
        const __nv_bfloat16* Al = As + (buf*2+1)*BM*APAD;
        const __nv_bfloat16* Bh = Bs + (buf*2+0)*BKF*BPAD;
        const __nv_bfloat16* Bl = Bs + (buf*2+1)*BKF*BPAD;

        int arow = wm*32 + (lane & 15);
        int aoff = (lane >> 4) * 8;
        int brow = lane & 15;
        int boff = wn*32 + (lane >> 4) * 8;

        #pragma unroll
        for (int kk = 0; kk < BKF; kk += 16) {
            uint32_t ah[2][4], al[2][4], bh[2][4], bl[2][4];
            #pragma unroll
            for (int mf = 0; mf < 2; mf++) {
                ldsm_x4(ah[mf], Ah + (arow + mf*16)*APAD + kk + aoff);
                ldsm_x4(al[mf], Al + (arow + mf*16)*APAD + kk + aoff);
            }
            #pragma unroll
            for (int gg = 0; gg < 2; gg++) {
                ldsm_x4t(bh[gg], Bh + (kk + brow)*BPAD + boff + gg*16);
                ldsm_x4t(bl[gg], Bl + (kk + brow)*BPAD + boff + gg*16);
            }
            #pragma unroll
            for (int mf = 0; mf < 2; mf++)
                #pragma unroll
                for (int nf = 0; nf < 4; nf++) {
                    uint32_t* bfh = &bh[nf>>1][(nf&1)*2];
                    uint32_t* bfl = &bl[nf>>1][(nf&1)*2];
                    mma_bf16(acc[mf][nf], ah[mf], bfh);
                    mma_bf16(acc[mf][nf], ah[mf], bfl);
                    mma_bf16(acc[mf][nf], al[mf], bfh);
                }
        }
        if (kt + 1 < nk) {
            int nbuf = buf ^ 1;
            __nv_bfloat16* nAh = As + (nbuf*2+0)*BM*APAD;
            __nv_bfloat16* nAl = As + (nbuf*2+1)*BM*APAD;
            __nv_bfloat16* nBh = Bs + (nbuf*2+0)*BKF*BPAD;
            __nv_bfloat16* nBl = Bs + (nbuf*2+1)*BKF*BPAD;
            #pragma unroll
            for (int i = 0; i < 4; i++) {
                uint32_t h, l;
                split2(pa[i].x, pa[i].y, h, l);
                *(uint32_t*)(nAh + ar*APAD + ac + 4*i)     = h;
                *(uint32_t*)(nAl + ar*APAD + ac + 4*i)     = l;
                split2(pa[i].z, pa[i].w, h, l);
                *(uint32_t*)(nAh + ar*APAD + ac + 4*i + 2) = h;
                *(uint32_t*)(nAl + ar*APAD + ac + 4*i + 2) = l;
            }
            #pragma unroll
            for (int i = 0; i < 2; i++) {
                uint32_t h, l;
                split2(pb[i].x, pb[i].y, h, l);
                *(uint32_t*)(nBh + br*BPAD + bc + 4*i)     = h;
                *(uint32_t*)(nBl + br*BPAD + bc + 4*i)     = l;
                split2(pb[i].z, pb[i].w, h, l);
                *(uint32_t*)(nBh + br*BPAD + bc + 4*i + 2) = h;
                *(uint32_t*)(nBl + br*BPAD + bc + 4*i + 2) = l;
            }
            __syncthreads();
        }
    }

    // epilogue
    int r0 = bm*BM + wm*32;
    int c0 = bn*BN + wn*32;
    #pragma unroll
    for (int mf = 0; mf < 2; mf++) {
        #pragma unroll
        for (int nf = 0; nf < 4; nf++) {
            int col = c0 + nf*8 + (lane & 3)*2;
            int row = r0 + mf*16 + (lane >> 2);
            float bx = __ldg(bias + col), by = __ldg(bias + col + 1);
            float v0 = acc[mf][nf][0] + bx;
            float v1 = acc[mf][nf][1] + by;
            float v2 = acc[mf][nf][2] + bx;
            float v3 = acc[mf][nf][3] + by;
            if (EPI == 1) {
                v0 = gelu_exact(v0); v1 = gelu_exact(v1);
                v2 = gelu_exact(v2); v3 = gelu_exact(v3);
            }
            size_t off0 = (size_t)row * N + col;
            size_t off1 = (size_t)(row + 8) * N + col;
            if (EPI == 2) {
                float2 rr0 = *(const float2*)(Res + off0);
                float2 rr1 = *(const float2*)(Res + off1);
                v0 += rr0.x; v1 += rr0.y;
                v2 += rr1.x; v3 += rr1.y;
            }
            *(float2*)(C + off0) = make_float2(v0, v1);
            *(float2*)(C + off1) = make_float2(v2, v3);
        }
    }
}

// ---------------- Windowed attention: one CTA per (window, head) ----------------
template<bool SHIFT>
__global__ __launch_bounds__(128)
void attn_kernel(const float* __restrict__ qkv,
                 const float* __restrict__ rpb,
                 float* __restrict__ out)
{
    extern __shared__ float sm[];
    float* sk = sm;
    float* sv = sk + 128*32;
    float* sp = sv + 128*32;
    int*   slab = (int*)(sp + 128*129);

    int n    = threadIdx.x;
    int head = blockIdx.y;
    int win  = blockIdx.x;
    int b  = win >> 8;
    int r  = win & 255;
    int wt = r >> 6, wh = (r >> 3) & 7, wwi = r & 7;
    int ti = n >> 6, hi = (n >> 3) & 7, wi  = n & 7;
    int pt = wt*2 + ti, ph = wh*8 + hi, pw = wwi*8 + wi;
    int t, h, w;
    if (SHIFT) { t = (pt + 1) & 7; h = (ph + 4) & 63; w = (pw + 4) & 63; }
    else       { t = pt;           h = ph;            w = pw; }
    int tok = ((b*TT + t)*HH + h)*WW + w;

    int mylab = 0;
    if (SHIFT) {
        int lt = pt < 6  ? 0 : (pt < 7  ? 1 : 2);
        int lh = ph < 56 ? 0 : (ph < 60 ? 1 : 2);
        int lw = pw < 56 ? 0 : (pw < 60 ? 1 : 2);
        mylab = lt*9 + lh*3 + lw;
        slab[n] = mylab;
    }

    const float* qp = qkv + (size_t)tok * QKV_N + head * HD;
    float qr[32];
    #pragma unroll
    for (int i = 0; i < 8; i++) {
        float4 qv = ((const float4*)qp)[i];
        qr[4*i+0] = qv.x * SCALE; qr[4*i+1] = qv.y * SCALE;
        qr[4*i+2] = qv.z * SCALE; qr[4*i+3] = qv.w * SCALE;
        float4 kv = ((const float4*)(qp + CC))[i];
        *(float4*)(sk + n*32 + 4*i) = kv;
        float4 vv = ((const float4*)(qp + 2*CC))[i];
        *(float4*)(sv + n*32 + 4*i) = vv;
    }
    __syncthreads();

    float* myrow = sp + n * 129;
    float mx = -1e30f;
    #pragma unroll 2
    for (int j = 0; j < 128; j++) {
        int tj = j >> 6, hj = (j >> 3) & 7, wj = j & 7;
        const float4* kr = (const float4*)(sk + j*32);
        float s0 = 0.f, s1 = 0.f, s2 = 0.f, s3 = 0.f;
        #pragma unroll
        for (int d = 0; d < 8; d++) {
            float4 kv = kr[d];
            s0 += qr[4*d+0] * kv.x;
            s1 += qr[4*d+1] * kv.y;
            s2 += qr[4*d+2] * kv.z;
            s3 += qr[4*d+3] * kv.w;
        }
        int rel = (ti - tj + 1)*225 + (hi - hj + 7)*15 + (wi - wj + 7);
        float s = (s0 + s1) + (s2 + s3) + __ldg(rpb + rel*NHEAD + head);
        if (SHIFT && slab[j] != mylab) s -= 100.0f;
        myrow[j] = s;
        mx = fmaxf(mx, s);
    }
    float sum = 0.f;
    #pragma unroll 4
    for (int j = 0; j < 128; j++) {
        float e = __expf(myrow[j] - mx);
        myrow[j] = e;
        sum += e;
    }
    float inv = 1.0f / sum;

    float o[32];
    #pragma unroll
    for (int d = 0; d < 32; d++) o[d] = 0.f;
    #pragma unroll 2
    for (int j = 0; j < 128; j++) {
        float p = myrow[j];
        const float4* vr = (const float4*)(sv + j*32);
        #pragma unroll
        for (int d = 0; d < 8; d++) {
            float4 vv = vr[d];
            o[4*d+0] += p * vv.x;
            o[4*d+1] += p * vv.y;
            o[4*d+2] += p * vv.z;
            o[4*d+3] += p * vv.w;
        }
    }
    float* op = out + (size_t)tok * CC + head * HD;
    #pragma unroll
    for (int i = 0; i < 8; i++) {
        float4 ov;
        ov.x = o[4*i+0]*inv; ov.y = o[4*i+1]*inv;
        ov.z = o[4*i+2]*inv; ov.w = o[4*i+3]*inv;
        ((float4*)op)[i] = ov;
    }
}

// ---------------- host orchestration ----------------
#define ATTN_SMEM ((2*128*32 + 128*129)*4 + 128*4)

extern "C" void kernel_launch(void* const* d_in, const int* in_sizes, int n_in,
                              void* d_out, int out_size)
{
    const float* x       = (const float*)d_in[0];
    const float* rpb1    = (const float*)d_in[1];
    const float* qkv_w1  = (const float*)d_in[2];
    const float* qkv_b1  = (const float*)d_in[3];
    const float* proj_w1 = (const float*)d_in[4];
    const float* proj_b1 = (const float*)d_in[5];
    const float* rpb2    = (const float*)d_in[6];
    const float* qkv_w2  = (const float*)d_in[7];
    const float* qkv_b2  = (const float*)d_in[8];
    const float* proj_w2 = (const float*)d_in[9];
    const float* proj_b2 = (const float*)d_in[10];
    const float* g1  = (const float*)d_in[11];
    const float* be1 = (const float*)d_in[12];
    const float* g2  = (const float*)d_in[13];
    const float* be2 = (const float*)d_in[14];
    const float* g3  = (const float*)d_in[15];
    const float* be3 = (const float*)d_in[16];
    const float* g4  = (const float*)d_in[17];
    const float* be4 = (const float*)d_in[18];
    const float* m1w1 = (const float*)d_in[19];
    const float* m1b1 = (const float*)d_in[20];
    const float* m1w2 = (const float*)d_in[21];
    const float* m1b2 = (const float*)d_in[22];
    const float* m2w1 = (const float*)d_in[23];
    const float* m2b1 = (const float*)d_in[24];
    const float* m2w2 = (const float*)d_in[25];
    const float* m2b2 = (const float*)d_in[26];
    float* out = (float*)d_out;

    float *xn, *qkvb, *att, *hid, *xb;
    cudaGetSymbolAddress((void**)&xn,   g_xn);
    cudaGetSymbolAddress((void**)&qkvb, g_qkv);
    cudaGetSymbolAddress((void**)&att,  g_att);
    cudaGetSymbolAddress((void**)&hid,  g_hid);
    cudaGetSymbolAddress((void**)&xb,   g_x);

    cudaFuncSetAttribute(attn_kernel<false>,
        cudaFuncAttributeMaxDynamicSharedMemorySize, ATTN_SMEM);
    cudaFuncSetAttribute(attn_kernel<true>,
        cudaFuncAttributeMaxDynamicSharedMemorySize, ATTN_SMEM);
    cudaFuncSetAttribute(hgemm_kernel<0>,
        cudaFuncAttributeMaxDynamicSharedMemorySize, GSMEM_BYTES);
    cudaFuncSetAttribute(hgemm_kernel<1>,
        cudaFuncAttributeMaxDynamicSharedMemorySize, GSMEM_BYTES);
    cudaFuncSetAttribute(hgemm_kernel<2>,
        cudaFuncAttributeMaxDynamicSharedMemorySize, GSMEM_BYTES);

    const int M = NTOK;
    dim3 lnGrid(M / 8);
    dim3 attnGrid(NWIN, NHEAD);

    // ---- block 1 ----
    ln_kernel<<<lnGrid, 256>>>(x, g1, be1, xn);
    hgemm_kernel<0><<<dim3(QKV_N/BN, M/BM), 256, GSMEM_BYTES>>>(M, QKV_N, CC, xn, qkv_w1, qkv_b1, nullptr, qkvb);
    attn_kernel<false><<<attnGrid, 128, ATTN_SMEM>>>(qkvb, rpb1, att);
    hgemm_kernel<2><<<dim3(CC/BN, M/BM), 256, GSMEM_BYTES>>>(M, CC, CC, att, proj_w1, proj_b1, x, xb);
    ln_kernel<<<lnGrid, 256>>>(xb, g2, be2, xn);
    hgemm_kernel<1><<<dim3(HID/BN, M/BM), 256, GSMEM_BYTES>>>(M, HID, CC, xn, m1w1, m1b1, nullptr, hid);
    hgemm_kernel<2><<<dim3(CC/BN, M/BM), 256, GSMEM_BYTES>>>(M, CC, HID, hid, m1w2, m1b2, xb, xb);

    // ---- block 2 (shifted) ----
    ln_kernel<<<lnGrid, 256>>>(xb, g3, be3, xn);
    hgemm_kernel<0><<<dim3(QKV_N/BN, M/BM), 256, GSMEM_BYTES>>>(M, QKV_N, CC, xn, qkv_w2, qkv_b2, nullptr, qkvb);
    attn_kernel<true><<<attnGrid, 128, ATTN_SMEM>>>(qkvb, rpb2, att);
    hgemm_kernel<2><<<dim3(CC/BN, M/BM), 256, GSMEM_BYTES>>>(M, CC, CC, att, proj_w2, proj_b2, xb, xb);
    ln_kernel<<<lnGrid, 256>>>(xb, g4, be4, xn);
    hgemm_kernel<1><<<dim3(HID/BN, M/BM), 256, GSMEM_BYTES>>>(M, HID, CC, xn, m2w1, m2b1, nullptr, hid);
    hgemm_kernel<2><<<dim3(CC/BN, M/BM), 256, GSMEM_BYTES>>>(M, CC, HID, hid, m2w2, m2b2, xb, out);
}

// round 3
// speedup vs baseline: 1.8911x; 1.2673x over previous
#include <cuda_runtime.h>
#include <cuda_bf16.h>
#include <cuda_fp16.h>
#include <cstdint>

// Problem constants
#define BATCH 4
#define TT 8
#define HH 64
#define WW 64
#define CC 256
#define NTOK (BATCH*TT*HH*WW)          // 131072 tokens
#define NHEAD 8
#define HD 32
#define NWIN 1024
#define QKV_N 768
#define HID 512
#define SCALE 0.17677669529663687f     // 1/sqrt(32)

// ---------------- scratch ----------------
__device__ float g_xn [NTOK * CC];
__device__ float g_qkv[NTOK * QKV_N];
__device__ float g_att[NTOK * CC];
__device__ float g_hid[NTOK * HID];
__device__ float g_x  [NTOK * CC];

// ---------------- LayerNorm: one warp per token ----------------
__global__ __launch_bounds__(256)
void ln_kernel(const float* __restrict__ x, const float* __restrict__ g,
               const float* __restrict__ b, float* __restrict__ out)
{
    int gw   = (blockIdx.x * blockDim.x + threadIdx.x) >> 5;
    int lane = threadIdx.x & 31;
    if (gw >= NTOK) return;
    const float4* row = (const float4*)(x + (size_t)gw * CC);
    float4 v0 = row[lane];
    float4 v1 = row[lane + 32];
    float s = v0.x+v0.y+v0.z+v0.w + v1.x+v1.y+v1.z+v1.w;
    float q = v0.x*v0.x+v0.y*v0.y+v0.z*v0.z+v0.w*v0.w
            + v1.x*v1.x+v1.y*v1.y+v1.z*v1.z+v1.w*v1.w;
    #pragma unroll
    for (int o = 16; o > 0; o >>= 1) {
        s += __shfl_xor_sync(0xffffffffu, s, o);
        q += __shfl_xor_sync(0xffffffffu, q, o);
    }
    float mean = s * (1.0f/256.0f);
    float var  = q * (1.0f/256.0f) - mean*mean;
    float rstd = rsqrtf(var + 1e-5f);
    const float4* g4 = (const float4*)g;
    const float4* b4 = (const float4*)b;
    float4 ga = g4[lane], gb2 = g4[lane+32];
    float4 ba = b4[lane], bb2 = b4[lane+32];
    float4 o0, o1;
    o0.x = (v0.x-mean)*rstd*ga.x  + ba.x;
    o0.y = (v0.y-mean)*rstd*ga.y  + ba.y;
    o0.z = (v0.z-mean)*rstd*ga.z  + ba.z;
    o0.w = (v0.w-mean)*rstd*ga.w  + ba.w;
    o1.x = (v1.x-mean)*rstd*gb2.x + bb2.x;
    o1.y = (v1.y-mean)*rstd*gb2.y + bb2.y;
    o1.z = (v1.z-mean)*rstd*gb2.z + bb2.z;
    o1.w = (v1.w-mean)*rstd*gb2.w + bb2.w;
    float4* orow = (float4*)(out + (size_t)gw * CC);
    orow[lane]      = o0;
    orow[lane + 32] = o1;
}

// ---------------- fp16 split-A tensor-core GEMM ----------------
// C = (A_hi + A_lo) @ B_h + bias (+gelu | +residual); A split into two fp16,
// B single fp16 (error ~1.5e-4 rel, dominated by B rounding).
#define BM 128
#define BN 128
#define BKF 32
#define ASTR 40     // halves per A smem row (16B-aligned, ldsm conflict-free)
#define BSTR 136    // halves per B smem row
#define GSMEM_BYTES ((2*2*BM*ASTR + 2*BKF*BSTR) * 2)

__device__ __forceinline__ float gelu_exact(float x) {
    return 0.5f * x * (1.0f + erff(x * 0.7071067811865475f));
}

__device__ __forceinline__ void ldsm_x4(uint32_t* r, const __half* p) {
    uint32_t a = (uint32_t)__cvta_generic_to_shared(p);
    asm volatile("ldmatrix.sync.aligned.m8n8.x4.shared.b16 {%0,%1,%2,%3}, [%4];"
        : "=r"(r[0]), "=r"(r[1]), "=r"(r[2]), "=r"(r[3]) : "r"(a));
}
__device__ __forceinline__ void ldsm_x4t(uint32_t* r, const __half* p) {
    uint32_t a = (uint32_t)__cvta_generic_to_shared(p);
    asm volatile("ldmatrix.sync.aligned.m8n8.x4.trans.shared.b16 {%0,%1,%2,%3}, [%4];"
        : "=r"(r[0]), "=r"(r[1]), "=r"(r[2]), "=r"(r[3]) : "r"(a));
}
__device__ __forceinline__ void mma_f16(float* c, const uint32_t* a, const uint32_t* b) {
    asm volatile(
        "mma.sync.aligned.m16n8k16.row.col.f32.f16.f16.f32 "
        "{%0,%1,%2,%3}, {%4,%5,%6,%7}, {%8,%9}, {%0,%1,%2,%3};"
        : "+f"(c[0]), "+f"(c[1]), "+f"(c[2]), "+f"(c[3])
        : "r"(a[0]), "r"(a[1]), "r"(a[2]), "r"(a[3]), "r"(b[0]), "r"(b[1]));
}
// split two fp32 into fp16 hi pair + fp16 lo pair (packed)
__device__ __forceinline__ void split2h(float x0, float x1, uint32_t& h, uint32_t& l) {
    __half h0 = __float2half_rn(x0);
    __half h1 = __float2half_rn(x1);
    __half l0 = __float2half_rn(x0 - __half2float(h0));
    __half l1 = __float2half_rn(x1 - __half2float(h1));
    uint16_t uh0 = *(uint16_t*)&h0, uh1 = *(uint16_t*)&h1;
    uint16_t ul0 = *(uint16_t*)&l0, ul1 = *(uint16_t*)&l1;
    h = (uint32_t)uh0 | ((uint32_t)uh1 << 16);
    l = (uint32_t)ul0 | ((uint32_t)ul1 << 16);
}
__device__ __forceinline__ uint32_t pack2h(float x0, float x1) {
    __half2 p = __floats2half2_rn(x0, x1);
    return *(uint32_t*)&p;
}

template<int EPI>   // 0=bias, 1=bias+gelu, 2=bias+residual
__global__ __launch_bounds__(256, 2)
void hgemm_kernel(int M, int N, int K,
                  const float* __restrict__ A,
                  const float* __restrict__ B,
                  const float* __restrict__ bias,
                  const float* __restrict__ Res,
                  float* __restrict__ C)
{
    extern __shared__ __half smg[];
    __half* As = smg;                         // [2 buf][2 split][BM][ASTR]
    __half* Bs = smg + 2*2*BM*ASTR;           // [2 buf][BKF][BSTR]

    int tid  = threadIdx.x;
    int bm   = blockIdx.y, bn = blockIdx.x;
    int warp = tid >> 5, lane = tid & 31;
    int wm   = warp >> 1, wn = warp & 1;      // 4 x 2 warps, warp tile 32x64

    const float* Ab = A + (size_t)bm * BM * K;
    const float* Bb = B + bn * BN;

    int ar = tid >> 1, ac = (tid & 1) * 16;   // A: 128r x 32c fp32, 16 f/thread
    int br = tid >> 3, bc = (tid & 7) * 16;   // B: 32r x 128c fp32, 16 f/thread

    float acc[2][8][4];
    #pragma unroll
    for (int i = 0; i < 2; i++)
        #pragma unroll
        for (int j = 0; j < 8; j++)
            #pragma unroll
            for (int k = 0; k < 4; k++) acc[i][j][k] = 0.0f;

    float4 pa[4], pb[4];
    #pragma unroll
    for (int i = 0; i < 4; i++)
        pa[i] = *(const float4*)(Ab + (size_t)ar * K + ac + 4*i);
    #pragma unroll
    for (int i = 0; i < 4; i++)
        pb[i] = *(const float4*)(Bb + (size_t)br * N + bc + 4*i);

    // store tile 0
    {
        __half* Ah = As;
        __half* Al = As + BM*ASTR;
        __half* Bh = Bs;
        #pragma unroll
        for (int i = 0; i < 4; i++) {
            uint32_t h, l;
            split2h(pa[i].x, pa[i].y, h, l);
            *(uint32_t*)(Ah + ar*ASTR + ac + 4*i)     = h;
            *(uint32_t*)(Al + ar*ASTR + ac + 4*i)     = l;
            split2h(pa[i].z, pa[i].w, h, l);
            *(uint32_t*)(Ah + ar*ASTR + ac + 4*i + 2) = h;
            *(uint32_t*)(Al + ar*ASTR + ac + 4*i + 2) = l;
        }
        #pragma unroll
        for (int i = 0; i < 4; i++) {
            *(uint32_t*)(Bh + br*BSTR + bc + 4*i)     = pack2h(pb[i].x, pb[i].y);
            *(uint32_t*)(Bh + br*BSTR + bc + 4*i + 2) = pack2h(pb[i].z, pb[i].w);
        }
    }
    __syncthreads();

    int nk = K / BKF;
    for (int kt = 0; kt < nk; kt++) {
        if (kt + 1 < nk) {
            #pragma unroll
            for (int i = 0; i < 4; i++)
                pa[i] = *(const float4*)(Ab + (size_t)ar * K + (kt+1)*BKF + ac + 4*i);
            #pragma unroll
            for (int i = 0; i < 4; i++)
                pb[i] = *(const float4*)(Bb + (size_t)((kt+1)*BKF + br) * N + bc + 4*i);
        }
        int buf = kt & 1;
        const __half* Ah = As + (buf*2+0)*BM*ASTR;
        const __half* Al = As + (buf*2+1)*BM*ASTR;
        const __half* Bh = Bs + buf*BKF*BSTR;

        int arow = wm*32 + (lane & 15);
        int aoff = (lane >> 4) * 8;
        int brow = lane & 15;
        int bcol = wn*64 + (lane >> 4) * 8;

        #pragma unroll
        for (int kk = 0; kk < BKF; kk += 16) {
            uint32_t ah[2][4], al[2][4], bb[4][4];
            #pragma unroll
            for (int mf = 0; mf < 2; mf++) {
                ldsm_x4(ah[mf], Ah + (arow + mf*16)*ASTR + kk + aoff);
                ldsm_x4(al[mf], Al + (arow + mf*16)*ASTR + kk + aoff);
            }
            #pragma unroll
            for (int gg = 0; gg < 4; gg++)
                ldsm_x4t(bb[gg], Bh + (kk + brow)*BSTR + bcol + gg*16);
            #pragma unroll
            for (int mf = 0; mf < 2; mf++)
                #pragma unroll
                for (int nf = 0; nf < 8; nf++) {
                    uint32_t* bf = &bb[nf>>1][(nf&1)*2];
                    mma_f16(acc[mf][nf], ah[mf], bf);
                    mma_f16(acc[mf][nf], al[mf], bf);
                }
        }
        if (kt + 1 < nk) {
            int nbuf = buf ^ 1;
            __half* nAh = As + (nbuf*2+0)*BM*ASTR;
            __half* nAl = As + (nbuf*2+1)*BM*ASTR;
            __half* nBh = Bs + nbuf*BKF*BSTR;
            #pragma unroll
            for (int i = 0; i < 4; i++) {
                uint32_t h, l;
                split2h(pa[i].x, pa[i].y, h, l);
                *(uint32_t*)(nAh + ar*ASTR + ac + 4*i)     = h;
                *(uint32_t*)(nAl + ar*ASTR + ac + 4*i)     = l;
                split2h(pa[i].z, pa[i].w, h, l);
                *(uint32_t*)(nAh + ar*ASTR + ac + 4*i + 2) = h;
                *(uint32_t*)(nAl + ar*ASTR + ac + 4*i + 2) = l;
            }
            #pragma unroll
            for (int i = 0; i < 4; i++) {
                *(uint32_t*)(nBh + br*BSTR + bc + 4*i)     = pack2h(pb[i].x, pb[i].y);
                *(uint32_t*)(nBh + br*BSTR + bc + 4*i + 2) = pack2h(pb[i].z, pb[i].w);
            }
            __syncthreads();
        }
    }

    // epilogue
    int r0 = bm*BM + wm*32;
    int c0 = bn*BN + wn*64;
    #pragma unroll
    for (int mf = 0; mf < 2; mf++) {
        #pragma unroll
        for (int nf = 0; nf < 8; nf++) {
            int col = c0 + nf*8 + (lane & 3)*2;
            int row = r0 + mf*16 + (lane >> 2);
            float bx = __ldg(bias + col), by = __ldg(bias + col + 1);
            float v0 = acc[mf][nf][0] + bx;
            float v1 = acc[mf][nf][1] + by;
            float v2 = acc[mf][nf][2] + bx;
            float v3 = acc[mf][nf][3] + by;
            if (EPI == 1) {
                v0 = gelu_exact(v0); v1 = gelu_exact(v1);
                v2 = gelu_exact(v2); v3 = gelu_exact(v3);
            }
            size_t off0 = (size_t)row * N + col;
            size_t off1 = (size_t)(row + 8) * N + col;
            if (EPI == 2) {
                float2 rr0 = *(const float2*)(Res + off0);
                float2 rr1 = *(const float2*)(Res + off1);
                v0 += rr0.x; v1 += rr0.y;
                v2 += rr1.x; v3 += rr1.y;
            }
            *(float2*)(C + off0) = make_float2(v0, v1);
            *(float2*)(C + off1) = make_float2(v2, v3);
        }
    }
}

// ---------------- Windowed attention: one CTA per (window, head) ----------------
template<bool SHIFT>
__global__ __launch_bounds__(128)
void attn_kernel(const float* __restrict__ qkv,
                 const float* __restrict__ rpb,
                 float* __restrict__ out)
{
    extern __shared__ float sm[];
    float* sk = sm;                       // [128][32]
    float* sv = sk + 128*32;              // [128][32]
    float* sp = sv + 128*32;              // [128][129]
    float* rbias = sp + 128*129;          // [675] head slice of rpb
    int*   slab  = (int*)(rbias + 676);   // [128]

    int n    = threadIdx.x;
    int head = blockIdx.y;
    int win  = blockIdx.x;
    int b  = win >> 8;
    int r  = win & 255;
    int wt = r >> 6, wh = (r >> 3) & 7, wwi = r & 7;
    int ti = n >> 6, hi = (n >> 3) & 7, wi  = n & 7;
    int pt = wt*2 + ti, ph = wh*8 + hi, pw = wwi*8 + wi;
    int t, h, w;
    if (SHIFT) { t = (pt + 1) & 7; h = (ph + 4) & 63; w = (pw + 4) & 63; }
    else       { t = pt;           h = ph;            w = pw; }
    int tok = ((b*TT + t)*HH + h)*WW + w;

    int mylab = 0;
    if (SHIFT) {
        int lt = pt < 6  ? 0 : (pt < 7  ? 1 : 2);
        int lh = ph < 56 ? 0 : (ph < 60 ? 1 : 2);
        int lw = pw < 56 ? 0 : (pw < 60 ? 1 : 2);
        mylab = lt*9 + lh*3 + lw;
        slab[n] = mylab;
    }

    // stage rpb slice for this head
    #pragma unroll
    for (int i = n; i < 675; i += 128)
        rbias[i] = __ldg(rpb + i*NHEAD + head);

    const float* qp = qkv + (size_t)tok * QKV_N + head * HD;
    float qr[32];
    #pragma unroll
    for (int i = 0; i < 8; i++) {
        float4 qv = ((const float4*)qp)[i];
        qr[4*i+0] = qv.x * SCALE; qr[4*i+1] = qv.y * SCALE;
        qr[4*i+2] = qv.z * SCALE; qr[4*i+3] = qv.w * SCALE;
        float4 kv = ((const float4*)(qp + CC))[i];
        *(float4*)(sk + n*32 + 4*i) = kv;
        float4 vv = ((const float4*)(qp + 2*CC))[i];
        *(float4*)(sv + n*32 + 4*i) = vv;
    }
    __syncthreads();

    float* myrow = sp + n * 129;
    float mx = -1e30f;
    #pragma unroll 2
    for (int j = 0; j < 128; j++) {
        int tj = j >> 6, hj = (j >> 3) & 7, wj = j & 7;
        const float4* kr = (const float4*)(sk + j*32);
        float s0 = 0.f, s1 = 0.f, s2 = 0.f, s3 = 0.f;
        #pragma unroll
        for (int d = 0; d < 8; d++) {
            float4 kv = kr[d];
            s0 += qr[4*d+0] * kv.x;
            s1 += qr[4*d+1] * kv.y;
            s2 += qr[4*d+2] * kv.z;
            s3 += qr[4*d+3] * kv.w;
        }
        int rel = (ti - tj + 1)*225 + (hi - hj + 7)*15 + (wi - wj + 7);
        float s = (s0 + s1) + (s2 + s3) + rbias[rel];
        if (SHIFT && slab[j] != mylab) s -= 100.0f;
        myrow[j] = s;
        mx = fmaxf(mx, s);
    }
    float sum = 0.f;
    #pragma unroll 4
    for (int j = 0; j < 128; j++) {
        float e = __expf(myrow[j] - mx);
        myrow[j] = e;
        sum += e;
    }
    float inv = 1.0f / sum;

    float o[32];
    #pragma unroll
    for (int d = 0; d < 32; d++) o[d] = 0.f;
    #pragma unroll 2
    for (int j = 0; j < 128; j++) {
        float p = myrow[j];
        const float4* vr = (const float4*)(sv + j*32);
        #pragma unroll
        for (int d = 0; d < 8; d++) {
            float4 vv = vr[d];
            o[4*d+0] += p * vv.x;
            o[4*d+1] += p * vv.y;
            o[4*d+2] += p * vv.z;
            o[4*d+3] += p * vv.w;
        }
    }
    float* op = out + (size_t)tok * CC + head * HD;
    #pragma unroll
    for (int i = 0; i < 8; i++) {
        float4 ov;
        ov.x = o[4*i+0]*inv; ov.y = o[4*i+1]*inv;
        ov.z = o[4*i+2]*inv; ov.w = o[4*i+3]*inv;
        ((float4*)op)[i] = ov;
    }
}

// ---------------- host orchestration ----------------
#define ATTN_SMEM ((2*128*32 + 128*129 + 676)*4 + 128*4)

extern "C" void kernel_launch(void* const* d_in, const int* in_sizes, int n_in,
                              void* d_out, int out_size)
{
    const float* x       = (const float*)d_in[0];
    const float* rpb1    = (const float*)d_in[1];
    const float* qkv_w1  = (const float*)d_in[2];
    const float* qkv_b1  = (const float*)d_in[3];
    const float* proj_w1 = (const float*)d_in[4];
    const float* proj_b1 = (const float*)d_in[5];
    const float* rpb2    = (const float*)d_in[6];
    const float* qkv_w2  = (const float*)d_in[7];
    const float* qkv_b2  = (const float*)d_in[8];
    const float* proj_w2 = (const float*)d_in[9];
    const float* proj_b2 = (const float*)d_in[10];
    const float* g1  = (const float*)d_in[11];
    const float* be1 = (const float*)d_in[12];
    const float* g2  = (const float*)d_in[13];
    const float* be2 = (const float*)d_in[14];
    const float* g3  = (const float*)d_in[15];
    const float* be3 = (const float*)d_in[16];
    const float* g4  = (const float*)d_in[17];
    const float* be4 = (const float*)d_in[18];
    const float* m1w1 = (const float*)d_in[19];
    const float* m1b1 = (const float*)d_in[20];
    const float* m1w2 = (const float*)d_in[21];
    const float* m1b2 = (const float*)d_in[22];
    const float* m2w1 = (const float*)d_in[23];
    const float* m2b1 = (const float*)d_in[24];
    const float* m2w2 = (const float*)d_in[25];
    const float* m2b2 = (const float*)d_in[26];
    float* out = (float*)d_out;

    float *xn, *qkvb, *att, *hid, *xb;
    cudaGetSymbolAddress((void**)&xn,   g_xn);
    cudaGetSymbolAddress((void**)&qkvb, g_qkv);
    cudaGetSymbolAddress((void**)&att,  g_att);
    cudaGetSymbolAddress((void**)&hid,  g_hid);
    cudaGetSymbolAddress((void**)&xb,   g_x);

    cudaFuncSetAttribute(attn_kernel<false>,
        cudaFuncAttributeMaxDynamicSharedMemorySize, ATTN_SMEM);
    cudaFuncSetAttribute(attn_kernel<true>,
        cudaFuncAttributeMaxDynamicSharedMemorySize, ATTN_SMEM);
    cudaFuncSetAttribute(hgemm_kernel<0>,
        cudaFuncAttributeMaxDynamicSharedMemorySize, GSMEM_BYTES);
    cudaFuncSetAttribute(hgemm_kernel<1>,
        cudaFuncAttributeMaxDynamicSharedMemorySize, GSMEM_BYTES);
    cudaFuncSetAttribute(hgemm_kernel<2>,
        cudaFuncAttributeMaxDynamicSharedMemorySize, GSMEM_BYTES);

    const int M = NTOK;
    dim3 lnGrid(M / 8);
    dim3 attnGrid(NWIN, NHEAD);

    // ---- block 1 ----
    ln_kernel<<<lnGrid, 256>>>(x, g1, be1, xn);
    hgemm_kernel<0><<<dim3(QKV_N/BN, M/BM), 256, GSMEM_BYTES>>>(M, QKV_N, CC, xn, qkv_w1, qkv_b1, nullptr, qkvb);
    attn_kernel<false><<<attnGrid, 128, ATTN_SMEM>>>(qkvb, rpb1, att);
    hgemm_kernel<2><<<dim3(CC/BN, M/BM), 256, GSMEM_BYTES>>>(M, CC, CC, att, proj_w1, proj_b1, x, xb);
    ln_kernel<<<lnGrid, 256>>>(xb, g2, be2, xn);
    hgemm_kernel<1><<<dim3(HID/BN, M/BM), 256, GSMEM_BYTES>>>(M, HID, CC, xn, m1w1, m1b1, nullptr, hid);
    hgemm_kernel<2><<<dim3(CC/BN, M/BM), 256, GSMEM_BYTES>>>(M, CC, HID, hid, m1w2, m1b2, xb, xb);

    // ---- block 2 (shifted) ----
    ln_kernel<<<lnGrid, 256>>>(xb, g3, be3, xn);
    hgemm_kernel<0><<<dim3(QKV_N/BN, M/BM), 256, GSMEM_BYTES>>>(M, QKV_N, CC, xn, qkv_w2, qkv_b2, nullptr, qkvb);
    attn_kernel<true><<<attnGrid, 128, ATTN_SMEM>>>(qkvb, rpb2, att);
    hgemm_kernel<2><<<dim3(CC/BN, M/BM), 256, GSMEM_BYTES>>>(M, CC, CC, att, proj_w2, proj_b2, xb, xb);
    ln_kernel<<<lnGrid, 256>>>(xb, g4, be4, xn);
    hgemm_kernel<1><<<dim3(HID/BN, M/BM), 256, GSMEM_BYTES>>>(M, HID, CC, xn, m2w1, m2b1, nullptr, hid);
    hgemm_kernel<2><<<dim3(CC/BN, M/BM), 256, GSMEM_BYTES>>>(M, CC, HID, hid, m2w2, m2b2, xb, out);
}

// round 5
// speedup vs baseline: 2.3675x; 1.2519x over previous
#include <cuda_runtime.h>
#include <cuda_bf16.h>
#include <cuda_fp16.h>
#include <cstdint>

// Problem constants
#define BATCH 4
#define TT 8
#define HH 64
#define WW 64
#define CC 256
#define NTOK (BATCH*TT*HH*WW)          // 131072 tokens
#define NHEAD 8
#define HD 32
#define NWIN 1024
#define QKV_N 768
#define HID 512
#define SCALE 0.17677669529663687f     // 1/sqrt(32)

// ---------------- scratch ----------------
__device__ __half g_xnh [NTOK * CC];    // LN output (fp16, GEMM A)
__device__ __half g_qkvh[NTOK * QKV_N]; // qkv (fp16)
__device__ __half g_atth[NTOK * CC];    // attention output (fp16, GEMM A)
__device__ __half g_hidh[NTOK * HID];   // mlp hidden (fp16, GEMM A)
__device__ float  g_x   [NTOK * CC];    // running residual state (fp32)
__device__ __half g_wh  [1048576];      // fp16 weights (8 matrices)

// weight offsets in g_wh
#define OFF_QKV1 0
#define OFF_PROJ1 196608
#define OFF_M1W1 262144
#define OFF_M1W2 393216
#define OFF_QKV2 524288
#define OFF_PROJ2 720896
#define OFF_M2W1 786432
#define OFF_M2W2 917504

// ---------------- f32 -> f16 convert ----------------
__global__ __launch_bounds__(256)
void cvt_kernel(const float* __restrict__ src, __half* __restrict__ dst, int n)
{
    int i = (blockIdx.x * blockDim.x + threadIdx.x) * 4;
    if (i < n) {
        float4 v = *(const float4*)(src + i);
        __half2 a = __floats2half2_rn(v.x, v.y);
        __half2 b = __floats2half2_rn(v.z, v.w);
        uint32_t ua = *(uint32_t*)&a, ub = *(uint32_t*)&b;
        *(uint2*)(dst + i) = make_uint2(ua, ub);
    }
}

// ---------------- LayerNorm: one warp per token, fp16 out ----------------
// Each lane owns 8 CONSECUTIVE channels so the packed uint4 store is
// layout-correct (this was the R4 bug).
__global__ __launch_bounds__(256)
void ln_kernel(const float* __restrict__ x, const float* __restrict__ g,
               const float* __restrict__ b, __half* __restrict__ out)
{
    int gw   = (blockIdx.x * blockDim.x + threadIdx.x) >> 5;
    int lane = threadIdx.x & 31;
    if (gw >= NTOK) return;
    const float4* row = (const float4*)(x + (size_t)gw * CC);
    float4 v0 = row[2*lane];
    float4 v1 = row[2*lane + 1];
    float s = v0.x+v0.y+v0.z+v0.w + v1.x+v1.y+v1.z+v1.w;
    float q = v0.x*v0.x+v0.y*v0.y+v0.z*v0.z+v0.w*v0.w
            + v1.x*v1.x+v1.y*v1.y+v1.z*v1.z+v1.w*v1.w;
    #pragma unroll
    for (int o = 16; o > 0; o >>= 1) {
        s += __shfl_xor_sync(0xffffffffu, s, o);
        q += __shfl_xor_sync(0xffffffffu, q, o);
    }
    float mean = s * (1.0f/256.0f);
    float var  = q * (1.0f/256.0f) - mean*mean;
    float rstd = rsqrtf(var + 1e-5f);
    const float4* g4 = (const float4*)g;
    const float4* b4 = (const float4*)b;
    float4 ga = g4[2*lane], gb2 = g4[2*lane + 1];
    float4 ba = b4[2*lane], bb2 = b4[2*lane + 1];
    __half2 h0 = __floats2half2_rn((v0.x-mean)*rstd*ga.x  + ba.x,
                                   (v0.y-mean)*rstd*ga.y  + ba.y);
    __half2 h1 = __floats2half2_rn((v0.z-mean)*rstd*ga.z  + ba.z,
                                   (v0.w-mean)*rstd*ga.w  + ba.w);
    __half2 h2 = __floats2half2_rn((v1.x-mean)*rstd*gb2.x + bb2.x,
                                   (v1.y-mean)*rstd*gb2.y + bb2.y);
    __half2 h3 = __floats2half2_rn((v1.z-mean)*rstd*gb2.z + bb2.z,
                                   (v1.w-mean)*rstd*gb2.w + bb2.w);
    uint4 pack = make_uint4(*(uint32_t*)&h0, *(uint32_t*)&h1,
                            *(uint32_t*)&h2, *(uint32_t*)&h3);
    ((uint4*)(out + (size_t)gw * CC))[lane] = pack;
}

// ---------------- pure-fp16 tensor-core GEMM, cp.async 4-stage ----------------
#define BM 128
#define BN 128
#define BK 32        // halves per k-stage
#define NSTAGE 4
#define ASTR 40      // halves per A smem row
#define BSTR 136     // halves per B smem row
#define STAGE_H (BM*ASTR + BK*BSTR)
#define GSMEM_BYTES (NSTAGE * STAGE_H * 2)

__device__ __forceinline__ float gelu_exact(float x) {
    return 0.5f * x * (1.0f + erff(x * 0.7071067811865475f));
}
__device__ __forceinline__ void ldsm_x4(uint32_t* r, const __half* p) {
    uint32_t a = (uint32_t)__cvta_generic_to_shared(p);
    asm volatile("ldmatrix.sync.aligned.m8n8.x4.shared.b16 {%0,%1,%2,%3}, [%4];"
        : "=r"(r[0]), "=r"(r[1]), "=r"(r[2]), "=r"(r[3]) : "r"(a));
}
__device__ __forceinline__ void ldsm_x4t(uint32_t* r, const __half* p) {
    uint32_t a = (uint32_t)__cvta_generic_to_shared(p);
    asm volatile("ldmatrix.sync.aligned.m8n8.x4.trans.shared.b16 {%0,%1,%2,%3}, [%4];"
        : "=r"(r[0]), "=r"(r[1]), "=r"(r[2]), "=r"(r[3]) : "r"(a));
}
__device__ __forceinline__ void mma_f16(float* c, const uint32_t* a, const uint32_t* b) {
    asm volatile(
        "mma.sync.aligned.m16n8k16.row.col.f32.f16.f16.f32 "
        "{%0,%1,%2,%3}, {%4,%5,%6,%7}, {%8,%9}, {%0,%1,%2,%3};"
        : "+f"(c[0]), "+f"(c[1]), "+f"(c[2]), "+f"(c[3])
        : "r"(a[0]), "r"(a[1]), "r"(a[2]), "r"(a[3]), "r"(b[0]), "r"(b[1]));
}
__device__ __forceinline__ void cpa16(const __half* g, __half* s) {
    uint32_t sa = (uint32_t)__cvta_generic_to_shared(s);
    asm volatile("cp.async.cg.shared.global [%0], [%1], 16;" :: "r"(sa), "l"(g));
}

// EPI: 0=bias (fp16 out), 1=bias+gelu (fp16 out), 2=bias+residual (fp32 out)
template<int EPI>
__global__ __launch_bounds__(256, 2)
void hgemm_kernel(int M, int N, int K,
                  const __half* __restrict__ A,
                  const __half* __restrict__ B,
                  const float* __restrict__ bias,
                  const float* __restrict__ Res,
                  float* __restrict__ C,
                  __half* __restrict__ Ch)
{
    extern __shared__ __half smg[];

    int tid  = threadIdx.x;
    int bm   = blockIdx.y, bn = blockIdx.x;
    int warp = tid >> 5, lane = tid & 31;
    int wm   = warp >> 1, wn = warp & 1;      // 4x2 warps, warp tile 32x64

    const __half* Ab = A + (size_t)bm * BM * K;
    const __half* Bb = B + bn * BN;

    int ar = tid >> 2, ac = (tid & 3) * 8;    // A: 64 rows/pass x 32 halves
    int br = tid >> 4, bc = (tid & 15) * 8;   // B: 16 rows/pass x 128 halves

    float acc[2][8][4];
    #pragma unroll
    for (int i = 0; i < 2; i++)
        #pragma unroll
        for (int j = 0; j < 8; j++)
            #pragma unroll
            for (int k = 0; k < 4; k++) acc[i][j][k] = 0.0f;

    int nk = K / BK;

    // prologue: issue NSTAGE-1 stages
    #pragma unroll
    for (int s = 0; s < NSTAGE-1; s++) {
        __half* As = smg + s * STAGE_H;
        __half* Bs = As + BM*ASTR;
        cpa16(Ab + (size_t)ar * K + s*BK + ac,        As + ar*ASTR + ac);
        cpa16(Ab + (size_t)(ar+64) * K + s*BK + ac,   As + (ar+64)*ASTR + ac);
        cpa16(Bb + (size_t)(s*BK + br) * N + bc,      Bs + br*BSTR + bc);
        cpa16(Bb + (size_t)(s*BK + br + 16) * N + bc, Bs + (br+16)*BSTR + bc);
        asm volatile("cp.async.commit_group;");
    }

    int arow = wm*32 + (lane & 15);
    int aoff = (lane >> 4) * 8;
    int brow = lane & 15;
    int bcol = wn*64 + (lane >> 4) * 8;

    for (int kt = 0; kt < nk; kt++) {
        asm volatile("cp.async.wait_group %0;" :: "n"(NSTAGE-2));
        __syncthreads();

        int ns = kt + NSTAGE - 1;
        if (ns < nk) {
            __half* As = smg + (ns % NSTAGE) * STAGE_H;
            __half* Bs = As + BM*ASTR;
            cpa16(Ab + (size_t)ar * K + ns*BK + ac,        As + ar*ASTR + ac);
            cpa16(Ab + (size_t)(ar+64) * K + ns*BK + ac,   As + (ar+64)*ASTR + ac);
            cpa16(Bb + (size_t)(ns*BK + br) * N + bc,      Bs + br*BSTR + bc);
            cpa16(Bb + (size_t)(ns*BK + br + 16) * N + bc, Bs + (br+16)*BSTR + bc);
        }
        asm volatile("cp.async.commit_group;");

        const __half* As = smg + (kt % NSTAGE) * STAGE_H;
        const __half* Bs = As + BM*ASTR;

        #pragma unroll
        for (int kk = 0; kk < BK; kk += 16) {
            uint32_t af[2][4], bf[4][4];
            #pragma unroll
            for (int mf = 0; mf < 2; mf++)
                ldsm_x4(af[mf], As + (arow + mf*16)*ASTR + kk + aoff);
            #pragma unroll
            for (int gg = 0; gg < 4; gg++)
                ldsm_x4t(bf[gg], Bs + (kk + brow)*BSTR + bcol + gg*16);
            #pragma unroll
            for (int mf = 0; mf < 2; mf++)
                #pragma unroll
                for (int nf = 0; nf < 8; nf++)
                    mma_f16(acc[mf][nf], af[mf], &bf[nf>>1][(nf&1)*2]);
        }
    }

    // epilogue
    int r0 = bm*BM + wm*32;
    int c0 = bn*BN + wn*64;
    #pragma unroll
    for (int mf = 0; mf < 2; mf++) {
        #pragma unroll
        for (int nf = 0; nf < 8; nf++) {
            int col = c0 + nf*8 + (lane & 3)*2;
            int row = r0 + mf*16 + (lane >> 2);
            float bx = __ldg(bias + col), by = __ldg(bias + col + 1);
            float v0 = acc[mf][nf][0] + bx;
            float v1 = acc[mf][nf][1] + by;
            float v2 = acc[mf][nf][2] + bx;
            float v3 = acc[mf][nf][3] + by;
            size_t off0 = (size_t)row * N + col;
            size_t off1 = (size_t)(row + 8) * N + col;
            if (EPI == 1) {
                v0 = gelu_exact(v0); v1 = gelu_exact(v1);
                v2 = gelu_exact(v2); v3 = gelu_exact(v3);
            }
            if (EPI == 2) {
                float2 rr0 = *(const float2*)(Res + off0);
                float2 rr1 = *(const float2*)(Res + off1);
                v0 += rr0.x; v1 += rr0.y;
                v2 += rr1.x; v3 += rr1.y;
                *(float2*)(C + off0) = make_float2(v0, v1);
                *(float2*)(C + off1) = make_float2(v2, v3);
            } else {
                __half2 h0 = __floats2half2_rn(v0, v1);
                __half2 h1 = __floats2half2_rn(v2, v3);
                *(__half2*)(Ch + off0) = h0;
                *(__half2*)(Ch + off1) = h1;
            }
        }
    }
}

// ---------------- Windowed attention: one CTA per (window, head), fp16 I/O ----------------
template<bool SHIFT>
__global__ __launch_bounds__(128)
void attn_kernel(const __half* __restrict__ qkv,
                 const float* __restrict__ rpb,
                 __half* __restrict__ out)
{
    extern __shared__ float sm[];
    float* sk = sm;                       // [128][32]
    float* sv = sk + 128*32;              // [128][32]
    float* sp = sv + 128*32;              // [128][129]
    float* rbias = sp + 128*129;          // [675]
    int*   slab  = (int*)(rbias + 676);   // [128]

    int n    = threadIdx.x;
    int head = blockIdx.y;
    int win  = blockIdx.x;
    int b  = win >> 8;
    int r  = win & 255;
    int wt = r >> 6, wh = (r >> 3) & 7, wwi = r & 7;
    int ti = n >> 6, hi = (n >> 3) & 7, wi  = n & 7;
    int pt = wt*2 + ti, ph = wh*8 + hi, pw = wwi*8 + wi;
    int t, h, w;
    if (SHIFT) { t = (pt + 1) & 7; h = (ph + 4) & 63; w = (pw + 4) & 63; }
    else       { t = pt;           h = ph;            w = pw; }
    int tok = ((b*TT + t)*HH + h)*WW + w;

    int mylab = 0;
    if (SHIFT) {
        int lt = pt < 6  ? 0 : (pt < 7  ? 1 : 2);
        int lh = ph < 56 ? 0 : (ph < 60 ? 1 : 2);
        int lw = pw < 56 ? 0 : (pw < 60 ? 1 : 2);
        mylab = lt*9 + lh*3 + lw;
        slab[n] = mylab;
    }

    #pragma unroll
    for (int i = n; i < 675; i += 128)
        rbias[i] = __ldg(rpb + i*NHEAD + head);

    const __half2* qp2 = (const __half2*)(qkv + (size_t)tok * QKV_N + head * HD);
    float qr[32];
    #pragma unroll
    for (int i = 0; i < 16; i++) {
        float2 qf = __half22float2(qp2[i]);
        qr[2*i+0] = qf.x * SCALE;
        qr[2*i+1] = qf.y * SCALE;
        float2 kf = __half22float2(qp2[i + CC/2]);
        sk[n*32 + 2*i]   = kf.x;
        sk[n*32 + 2*i+1] = kf.y;
        float2 vf = __half22float2(qp2[i + CC]);
        sv[n*32 + 2*i]   = vf.x;
        sv[n*32 + 2*i+1] = vf.y;
    }
    __syncthreads();

    float* myrow = sp + n * 129;
    float mx = -1e30f;
    #pragma unroll 2
    for (int j = 0; j < 128; j++) {
        int tj = j >> 6, hj = (j >> 3) & 7, wj = j & 7;
        const float4* kr = (const float4*)(sk + j*32);
        float s0 = 0.f, s1 = 0.f, s2 = 0.f, s3 = 0.f;
        #pragma unroll
        for (int d = 0; d < 8; d++) {
            float4 kv = kr[d];
            s0 += qr[4*d+0] * kv.x;
            s1 += qr[4*d+1] * kv.y;
            s2 += qr[4*d+2] * kv.z;
            s3 += qr[4*d+3] * kv.w;
        }
        int rel = (ti - tj + 1)*225 + (hi - hj + 7)*15 + (wi - wj + 7);
        float s = (s0 + s1) + (s2 + s3) + rbias[rel];
        if (SHIFT && slab[j] != mylab) s -= 100.0f;
        myrow[j] = s;
        mx = fmaxf(mx, s);
    }
    float sum = 0.f;
    #pragma unroll 4
    for (int j = 0; j < 128; j++) {
        float e = __expf(myrow[j] - mx);
        myrow[j] = e;
        sum += e;
    }
    float inv = 1.0f / sum;

    float o[32];
    #pragma unroll
    for (int d = 0; d < 32; d++) o[d] = 0.f;
    #pragma unroll 2
    for (int j = 0; j < 128; j++) {
        float p = myrow[j];
        const float4* vr = (const float4*)(sv + j*32);
        #pragma unroll
        for (int d = 0; d < 8; d++) {
            float4 vv = vr[d];
            o[4*d+0] += p * vv.x;
            o[4*d+1] += p * vv.y;
            o[4*d+2] += p * vv.z;
            o[4*d+3] += p * vv.w;
        }
    }
    __half2* op2 = (__half2*)(out + (size_t)tok * CC + head * HD);
    #pragma unroll
    for (int i = 0; i < 16; i++)
        op2[i] = __floats2half2_rn(o[2*i]*inv, o[2*i+1]*inv);
}

// ---------------- host orchestration ----------------
#define ATTN_SMEM ((2*128*32 + 128*129 + 676)*4 + 128*4)

extern "C" void kernel_launch(void* const* d_in, const int* in_sizes, int n_in,
                              void* d_out, int out_size)
{
    const float* x       = (const float*)d_in[0];
    const float* rpb1    = (const float*)d_in[1];
    const float* qkv_w1  = (const float*)d_in[2];
    const float* qkv_b1  = (const float*)d_in[3];
    const float* proj_w1 = (const float*)d_in[4];
    const float* proj_b1 = (const float*)d_in[5];
    const float* rpb2    = (const float*)d_in[6];
    const float* qkv_w2  = (const float*)d_in[7];
    const float* qkv_b2  = (const float*)d_in[8];
    const float* proj_w2 = (const float*)d_in[9];
    const float* proj_b2 = (const float*)d_in[10];
    const float* g1  = (const float*)d_in[11];
    const float* be1 = (const float*)d_in[12];
    const float* g2  = (const float*)d_in[13];
    const float* be2 = (const float*)d_in[14];
    const float* g3  = (const float*)d_in[15];
    const float* be3 = (const float*)d_in[16];
    const float* g4  = (const float*)d_in[17];
    const float* be4 = (const float*)d_in[18];
    const float* m1w1 = (const float*)d_in[19];
    const float* m1b1 = (const float*)d_in[20];
    const float* m1w2 = (const float*)d_in[21];
    const float* m1b2 = (const float*)d_in[22];
    const float* m2w1 = (const float*)d_in[23];
    const float* m2b1 = (const float*)d_in[24];
    const float* m2w2 = (const float*)d_in[25];
    const float* m2b2 = (const float*)d_in[26];
    float* out = (float*)d_out;

    __half *xnh, *qkvh, *atth, *hidh, *wh;
    float *xb;
    cudaGetSymbolAddress((void**)&xnh,  g_xnh);
    cudaGetSymbolAddress((void**)&qkvh, g_qkvh);
    cudaGetSymbolAddress((void**)&atth, g_atth);
    cudaGetSymbolAddress((void**)&hidh, g_hidh);
    cudaGetSymbolAddress((void**)&xb,   g_x);
    cudaGetSymbolAddress((void**)&wh,   g_wh);

    cudaFuncSetAttribute(attn_kernel<false>,
        cudaFuncAttributeMaxDynamicSharedMemorySize, ATTN_SMEM);
    cudaFuncSetAttribute(attn_kernel<true>,
        cudaFuncAttributeMaxDynamicSharedMemorySize, ATTN_SMEM);
    cudaFuncSetAttribute(hgemm_kernel<0>,
        cudaFuncAttributeMaxDynamicSharedMemorySize, GSMEM_BYTES);
    cudaFuncSetAttribute(hgemm_kernel<1>,
        cudaFuncAttributeMaxDynamicSharedMemorySize, GSMEM_BYTES);
    cudaFuncSetAttribute(hgemm_kernel<2>,
        cudaFuncAttributeMaxDynamicSharedMemorySize, GSMEM_BYTES);

    // convert weights to fp16 (every launch; deterministic)
    cvt_kernel<<<(CC*QKV_N)/1024, 256>>>(qkv_w1,  wh + OFF_QKV1,  CC*QKV_N);
    cvt_kernel<<<(CC*CC)/1024,    256>>>(proj_w1, wh + OFF_PROJ1, CC*CC);
    cvt_kernel<<<(CC*HID)/1024,   256>>>(m1w1,    wh + OFF_M1W1,  CC*HID);
    cvt_kernel<<<(HID*CC)/1024,   256>>>(m1w2,    wh + OFF_M1W2,  HID*CC);
    cvt_kernel<<<(CC*QKV_N)/1024, 256>>>(qkv_w2,  wh + OFF_QKV2,  CC*QKV_N);
    cvt_kernel<<<(CC*CC)/1024,    256>>>(proj_w2, wh + OFF_PROJ2, CC*CC);
    cvt_kernel<<<(CC*HID)/1024,   256>>>(m2w1,    wh + OFF_M2W1,  CC*HID);
    cvt_kernel<<<(HID*CC)/1024,   256>>>(m2w2,    wh + OFF_M2W2,  HID*CC);

    const int M = NTOK;
    dim3 lnGrid(M / 8);
    dim3 attnGrid(NWIN, NHEAD);

    // ---- block 1 ----
    ln_kernel<<<lnGrid, 256>>>(x, g1, be1, xnh);
    hgemm_kernel<0><<<dim3(QKV_N/BN, M/BM), 256, GSMEM_BYTES>>>(M, QKV_N, CC, xnh, wh+OFF_QKV1, qkv_b1, nullptr, nullptr, qkvh);
    attn_kernel<false><<<attnGrid, 128, ATTN_SMEM>>>(qkvh, rpb1, atth);
    hgemm_kernel<2><<<dim3(CC/BN, M/BM), 256, GSMEM_BYTES>>>(M, CC, CC, atth, wh+OFF_PROJ1, proj_b1, x, xb, nullptr);
    ln_kernel<<<lnGrid, 256>>>(xb, g2, be2, xnh);
    hgemm_kernel<1><<<dim3(HID/BN, M/BM), 256, GSMEM_BYTES>>>(M, HID, CC, xnh, wh+OFF_M1W1, m1b1, nullptr, nullptr, hidh);
    hgemm_kernel<2><<<dim3(CC/BN, M/BM), 256, GSMEM_BYTES>>>(M, CC, HID, hidh, wh+OFF_M1W2, m1b2, xb, xb, nullptr);

    // ---- block 2 (shifted) ----
    ln_kernel<<<lnGrid, 256>>>(xb, g3, be3, xnh);
    hgemm_kernel<0><<<dim3(QKV_N/BN, M/BM), 256, GSMEM_BYTES>>>(M, QKV_N, CC, xnh, wh+OFF_QKV2, qkv_b2, nullptr, nullptr, qkvh);
    attn_kernel<true><<<attnGrid, 128, ATTN_SMEM>>>(qkvh, rpb2, atth);
    hgemm_kernel<2><<<dim3(CC/BN, M/BM), 256, GSMEM_BYTES>>>(M, CC, CC, atth, wh+OFF_PROJ2, proj_b2, xb, xb, nullptr);
    ln_kernel<<<lnGrid, 256>>>(xb, g4, be4, xnh);
    hgemm_kernel<1><<<dim3(HID/BN, M/BM), 256, GSMEM_BYTES>>>(M, HID, CC, xnh, wh+OFF_M2W1, m2b1, nullptr, nullptr, hidh);
    hgemm_kernel<2><<<dim3(CC/BN, M/BM), 256, GSMEM_BYTES>>>(M, CC, HID, hidh, wh+OFF_M2W2, m2b2, xb, out, nullptr);
}

// round 7
// speedup vs baseline: 4.6595x; 1.9681x over previous
#include <cuda_runtime.h>
#include <cuda_bf16.h>
#include <cuda_fp16.h>
#include <cstdint>

// Problem constants
#define BATCH 4
#define TT 8
#define HH 64
#define WW 64
#define CC 256
#define NTOK (BATCH*TT*HH*WW)          // 131072 tokens
#define NHEAD 8
#define HD 32
#define NWIN 1024
#define QKV_N 768
#define HID 512
#define SCALE 0.17677669529663687f     // 1/sqrt(32)

// ---------------- scratch ----------------
__device__ __half g_xnh [NTOK * CC];    // LN output (fp16, GEMM A)
__device__ __half g_qkvh[NTOK * QKV_N]; // qkv (fp16)
__device__ __half g_atth[NTOK * CC];    // attention output (fp16, GEMM A)
__device__ __half g_hidh[NTOK * HID];   // mlp hidden (fp16, GEMM A)
__device__ float  g_x   [NTOK * CC];    // running residual state (fp32)
__device__ __half g_wh  [1048576];      // fp16 weights (8 matrices)

#define OFF_QKV1 0
#define OFF_PROJ1 196608
#define OFF_M1W1 262144
#define OFF_M1W2 393216
#define OFF_QKV2 524288
#define OFF_PROJ2 720896
#define OFF_M2W1 786432
#define OFF_M2W2 917504

// ---------------- f32 -> f16 convert ----------------
__global__ __launch_bounds__(256)
void cvt_kernel(const float* __restrict__ src, __half* __restrict__ dst, int n)
{
    int i = (blockIdx.x * blockDim.x + threadIdx.x) * 4;
    if (i < n) {
        float4 v = *(const float4*)(src + i);
        __half2 a = __floats2half2_rn(v.x, v.y);
        __half2 b = __floats2half2_rn(v.z, v.w);
        uint32_t ua = *(uint32_t*)&a, ub = *(uint32_t*)&b;
        *(uint2*)(dst + i) = make_uint2(ua, ub);
    }
}

// ---------------- LayerNorm: one warp per token, fp16 out ----------------
__global__ __launch_bounds__(256)
void ln_kernel(const float* __restrict__ x, const float* __restrict__ g,
               const float* __restrict__ b, __half* __restrict__ out)
{
    int gw   = (blockIdx.x * blockDim.x + threadIdx.x) >> 5;
    int lane = threadIdx.x & 31;
    if (gw >= NTOK) return;
    const float4* row = (const float4*)(x + (size_t)gw * CC);
    float4 v0 = row[2*lane];
    float4 v1 = row[2*lane + 1];
    float s = v0.x+v0.y+v0.z+v0.w + v1.x+v1.y+v1.z+v1.w;
    float q = v0.x*v0.x+v0.y*v0.y+v0.z*v0.z+v0.w*v0.w
            + v1.x*v1.x+v1.y*v1.y+v1.z*v1.z+v1.w*v1.w;
    #pragma unroll
    for (int o = 16; o > 0; o >>= 1) {
        s += __shfl_xor_sync(0xffffffffu, s, o);
        q += __shfl_xor_sync(0xffffffffu, q, o);
    }
    float mean = s * (1.0f/256.0f);
    float var  = q * (1.0f/256.0f) - mean*mean;
    float rstd = rsqrtf(var + 1e-5f);
    const float4* g4 = (const float4*)g;
    const float4* b4 = (const float4*)b;
    float4 ga = g4[2*lane], gb2 = g4[2*lane + 1];
    float4 ba = b4[2*lane], bb2 = b4[2*lane + 1];
    __half2 h0 = __floats2half2_rn((v0.x-mean)*rstd*ga.x  + ba.x,
                                   (v0.y-mean)*rstd*ga.y  + ba.y);
    __half2 h1 = __floats2half2_rn((v0.z-mean)*rstd*ga.z  + ba.z,
                                   (v0.w-mean)*rstd*ga.w  + ba.w);
    __half2 h2 = __floats2half2_rn((v1.x-mean)*rstd*gb2.x + bb2.x,
                                   (v1.y-mean)*rstd*gb2.y + bb2.y);
    __half2 h3 = __floats2half2_rn((v1.z-mean)*rstd*gb2.z + bb2.z,
                                   (v1.w-mean)*rstd*gb2.w + bb2.w);
    uint4 pack = make_uint4(*(uint32_t*)&h0, *(uint32_t*)&h1,
                            *(uint32_t*)&h2, *(uint32_t*)&h3);
    ((uint4*)(out + (size_t)gw * CC))[lane] = pack;
}

// ---------------- shared MMA helpers ----------------
__device__ __forceinline__ void ldsm_x4(uint32_t* r, const __half* p) {
    uint32_t a = (uint32_t)__cvta_generic_to_shared(p);
    asm volatile("ldmatrix.sync.aligned.m8n8.x4.shared.b16 {%0,%1,%2,%3}, [%4];"
        : "=r"(r[0]), "=r"(r[1]), "=r"(r[2]), "=r"(r[3]) : "r"(a));
}
__device__ __forceinline__ void ldsm_x4t(uint32_t* r, const __half* p) {
    uint32_t a = (uint32_t)__cvta_generic_to_shared(p);
    asm volatile("ldmatrix.sync.aligned.m8n8.x4.trans.shared.b16 {%0,%1,%2,%3}, [%4];"
        : "=r"(r[0]), "=r"(r[1]), "=r"(r[2]), "=r"(r[3]) : "r"(a));
}
__device__ __forceinline__ void mma_f16(float* c, const uint32_t* a,
                                        uint32_t b0, uint32_t b1) {
    asm volatile(
        "mma.sync.aligned.m16n8k16.row.col.f32.f16.f16.f32 "
        "{%0,%1,%2,%3}, {%4,%5,%6,%7}, {%8,%9}, {%0,%1,%2,%3};"
        : "+f"(c[0]), "+f"(c[1]), "+f"(c[2]), "+f"(c[3])
        : "r"(a[0]), "r"(a[1]), "r"(a[2]), "r"(a[3]), "r"(b0), "r"(b1));
}
__device__ __forceinline__ uint32_t packh2(float x0, float x1) {
    __half2 p = __floats2half2_rn(x0, x1);
    return *(uint32_t*)&p;
}
__device__ __forceinline__ float gelu_exact(float x) {
    return 0.5f * x * (1.0f + erff(x * 0.7071067811865475f));
}
__device__ __forceinline__ void cpa16(const __half* g, __half* s) {
    uint32_t sa = (uint32_t)__cvta_generic_to_shared(s);
    asm volatile("cp.async.cg.shared.global [%0], [%1], 16;" :: "r"(sa), "l"(g));
}

// ---------------- pure-fp16 tensor-core GEMM, cp.async 4-stage ----------------
#define BM 128
#define BN 128
#define BK 32
#define NSTAGE 4
#define ASTR 40
#define BSTR 136
#define STAGE_H (BM*ASTR + BK*BSTR)
#define GSMEM_BYTES (NSTAGE * STAGE_H * 2)

template<int EPI>
__global__ __launch_bounds__(256, 2)
void hgemm_kernel(int M, int N, int K,
                  const __half* __restrict__ A,
                  const __half* __restrict__ B,
                  const float* __restrict__ bias,
                  const float* __restrict__ Res,
                  float* __restrict__ C,
                  __half* __restrict__ Ch)
{
    extern __shared__ __half smg[];

    int tid  = threadIdx.x;
    int bm   = blockIdx.y, bn = blockIdx.x;
    int warp = tid >> 5, lane = tid & 31;
    int wm   = warp >> 1, wn = warp & 1;

    const __half* Ab = A + (size_t)bm * BM * K;
    const __half* Bb = B + bn * BN;

    int ar = tid >> 2, ac = (tid & 3) * 8;
    int br = tid >> 4, bc = (tid & 15) * 8;

    float acc[2][8][4];
    #pragma unroll
    for (int i = 0; i < 2; i++)
        #pragma unroll
        for (int j = 0; j < 8; j++)
            #pragma unroll
            for (int k = 0; k < 4; k++) acc[i][j][k] = 0.0f;

    int nk = K / BK;

    #pragma unroll
    for (int s = 0; s < NSTAGE-1; s++) {
        __half* As = smg + s * STAGE_H;
        __half* Bs = As + BM*ASTR;
        cpa16(Ab + (size_t)ar * K + s*BK + ac,        As + ar*ASTR + ac);
        cpa16(Ab + (size_t)(ar+64) * K + s*BK + ac,   As + (ar+64)*ASTR + ac);
        cpa16(Bb + (size_t)(s*BK + br) * N + bc,      Bs + br*BSTR + bc);
        cpa16(Bb + (size_t)(s*BK + br + 16) * N + bc, Bs + (br+16)*BSTR + bc);
        asm volatile("cp.async.commit_group;");
    }

    int arow = wm*32 + (lane & 15);
    int aoff = (lane >> 4) * 8;
    int brow = lane & 15;
    int bcol = wn*64 + (lane >> 4) * 8;

    for (int kt = 0; kt < nk; kt++) {
        asm volatile("cp.async.wait_group %0;" :: "n"(NSTAGE-2));
        __syncthreads();

        int ns = kt + NSTAGE - 1;
        if (ns < nk) {
            __half* As = smg + (ns % NSTAGE) * STAGE_H;
            __half* Bs = As + BM*ASTR;
            cpa16(Ab + (size_t)ar * K + ns*BK + ac,        As + ar*ASTR + ac);
            cpa16(Ab + (size_t)(ar+64) * K + ns*BK + ac,   As + (ar+64)*ASTR + ac);
            cpa16(Bb + (size_t)(ns*BK + br) * N + bc,      Bs + br*BSTR + bc);
            cpa16(Bb + (size_t)(ns*BK + br + 16) * N + bc, Bs + (br+16)*BSTR + bc);
        }
        asm volatile("cp.async.commit_group;");

        const __half* As = smg + (kt % NSTAGE) * STAGE_H;
        const __half* Bs = As + BM*ASTR;

        #pragma unroll
        for (int kk = 0; kk < BK; kk += 16) {
            uint32_t af[2][4], bf[4][4];
            #pragma unroll
            for (int mf = 0; mf < 2; mf++)
                ldsm_x4(af[mf], As + (arow + mf*16)*ASTR + kk + aoff);
            #pragma unroll
            for (int gg = 0; gg < 4; gg++)
                ldsm_x4t(bf[gg], Bs + (kk + brow)*BSTR + bcol + gg*16);
            #pragma unroll
            for (int mf = 0; mf < 2; mf++)
                #pragma unroll
                for (int nf = 0; nf < 8; nf++)
                    mma_f16(acc[mf][nf], af[mf],
                            bf[nf>>1][(nf&1)*2], bf[nf>>1][(nf&1)*2+1]);
        }
    }

    int r0 = bm*BM + wm*32;
    int c0 = bn*BN + wn*64;
    #pragma unroll
    for (int mf = 0; mf < 2; mf++) {
        #pragma unroll
        for (int nf = 0; nf < 8; nf++) {
            int col = c0 + nf*8 + (lane & 3)*2;
            int row = r0 + mf*16 + (lane >> 2);
            float bx = __ldg(bias + col), by = __ldg(bias + col + 1);
            float v0 = acc[mf][nf][0] + bx;
            float v1 = acc[mf][nf][1] + by;
            float v2 = acc[mf][nf][2] + bx;
            float v3 = acc[mf][nf][3] + by;
            size_t off0 = (size_t)row * N + col;
            size_t off1 = (size_t)(row + 8) * N + col;
            if (EPI == 1) {
                v0 = gelu_exact(v0); v1 = gelu_exact(v1);
                v2 = gelu_exact(v2); v3 = gelu_exact(v3);
            }
            if (EPI == 2) {
                float2 rr0 = *(const float2*)(Res + off0);
                float2 rr1 = *(const float2*)(Res + off1);
                v0 += rr0.x; v1 += rr0.y;
                v2 += rr1.x; v3 += rr1.y;
                *(float2*)(C + off0) = make_float2(v0, v1);
                *(float2*)(C + off1) = make_float2(v2, v3);
            } else {
                *(__half2*)(Ch + off0) = __floats2half2_rn(v0, v1);
                *(__half2*)(Ch + off1) = __floats2half2_rn(v2, v3);
            }
        }
    }
}

// ---------------- Tensor-core windowed attention ----------------
// One CTA per (window, head), 128 threads (4 warps). S = Q K^T via MMA
// (fp32 accum in registers), bias/mask via rel = base_i - base_j + 337,
// quad-shuffle softmax, S-frags repacked in registers as A-frags for P V.
#define QSTR 40   // halves per smem row

template<bool SHIFT>
__global__ __launch_bounds__(128)
void attn_kernel(const __half* __restrict__ qkv,
                 const float* __restrict__ rpb,
                 __half* __restrict__ out)
{
    __shared__ __half sq [128*QSTR];
    __shared__ __half skk[128*QSTR];
    __shared__ __half svv[128*QSTR];
    __shared__ float rbias[675];
    __shared__ int   sbase[128];
    __shared__ int   slab [128];
    __shared__ int   stok [128];

    int n    = threadIdx.x;
    int lane = n & 31;
    int wm   = n >> 5;
    int head = blockIdx.y;
    int win  = blockIdx.x;
    int b  = win >> 8;
    int r  = win & 255;
    int wt = r >> 6, wh = (r >> 3) & 7, wwi = r & 7;
    int ti = n >> 6, hi = (n >> 3) & 7, wi  = n & 7;
    int pt = wt*2 + ti, ph = wh*8 + hi, pw = wwi*8 + wi;
    int t, h, w;
    if (SHIFT) { t = (pt + 1) & 7; h = (ph + 4) & 63; w = (pw + 4) & 63; }
    else       { t = pt;           h = ph;            w = pw; }
    int tok = ((b*TT + t)*HH + h)*WW + w;

    stok[n]  = tok;
    sbase[n] = ti*225 + hi*15 + wi;
    if (SHIFT) {
        int lt = pt < 6  ? 0 : (pt < 7  ? 1 : 2);
        int lh = ph < 56 ? 0 : (ph < 60 ? 1 : 2);
        int lw = pw < 56 ? 0 : (pw < 60 ? 1 : 2);
        slab[n] = lt*9 + lh*3 + lw;
    }
    for (int i = n; i < 675; i += 128)
        rbias[i] = __ldg(rpb + i*NHEAD + head);

    // stage q,k,v rows: 32 halves each = FOUR uint4 per tensor (R6 bug: only 2)
    {
        const uint4* qp = (const uint4*)(qkv + (size_t)tok * QKV_N + head * HD);
        #pragma unroll
        for (int i = 0; i < 4; i++) {
            *(uint4*)(sq  + n*QSTR + 8*i) = qp[i];
            *(uint4*)(skk + n*QSTR + 8*i) = qp[32 + i];
            *(uint4*)(svv + n*QSTR + 8*i) = qp[64 + i];
        }
    }
    __syncthreads();

    // ---- S = Q K^T : 2 m-tiles x 16 n8-tiles, fp32 accum ----
    float sc[2][16][4];
    #pragma unroll
    for (int mt = 0; mt < 2; mt++)
        #pragma unroll
        for (int nt = 0; nt < 16; nt++)
            #pragma unroll
            for (int v = 0; v < 4; v++) sc[mt][nt][v] = 0.0f;

    int lrow = lane & 15;
    int lcol = (lane >> 4) * 8;
    #pragma unroll
    for (int ks = 0; ks < 2; ks++) {
        uint32_t qa[2][4];
        #pragma unroll
        for (int mt = 0; mt < 2; mt++)
            ldsm_x4(qa[mt], sq + (wm*32 + mt*16 + lrow)*QSTR + ks*16 + lcol);
        #pragma unroll
        for (int ntp = 0; ntp < 8; ntp++) {
            uint32_t kb[4];
            ldsm_x4(kb, skk + (ntp*16 + lrow)*QSTR + ks*16 + lcol);
            #pragma unroll
            for (int mt = 0; mt < 2; mt++) {
                mma_f16(sc[mt][ntp*2],     qa[mt], kb[0], kb[2]);
                mma_f16(sc[mt][ntp*2 + 1], qa[mt], kb[1], kb[3]);
            }
        }
    }

    // ---- bias + mask + softmax ----
    int ibase[2][2], ilab[2][2];
    #pragma unroll
    for (int mt = 0; mt < 2; mt++)
        #pragma unroll
        for (int hh = 0; hh < 2; hh++) {
            int i = wm*32 + mt*16 + (lane >> 2) + hh*8;
            ibase[mt][hh] = sbase[i] + 337;
            if (SHIFT) ilab[mt][hh] = slab[i];
        }

    #pragma unroll
    for (int nt = 0; nt < 16; nt++) {
        int j0 = nt*8 + (lane & 3)*2;
        int bs0 = sbase[j0], bs1 = sbase[j0 + 1];
        int lb0 = 0, lb1 = 0;
        if (SHIFT) { lb0 = slab[j0]; lb1 = slab[j0 + 1]; }
        #pragma unroll
        for (int mt = 0; mt < 2; mt++)
            #pragma unroll
            for (int hh = 0; hh < 2; hh++) {
                float v0 = sc[mt][nt][hh*2]   * SCALE + rbias[ibase[mt][hh] - bs0];
                float v1 = sc[mt][nt][hh*2+1] * SCALE + rbias[ibase[mt][hh] - bs1];
                if (SHIFT) {
                    if (lb0 != ilab[mt][hh]) v0 -= 100.0f;
                    if (lb1 != ilab[mt][hh]) v1 -= 100.0f;
                }
                sc[mt][nt][hh*2]   = v0;
                sc[mt][nt][hh*2+1] = v1;
            }
    }

    float inv_[2][2];
    #pragma unroll
    for (int mt = 0; mt < 2; mt++)
        #pragma unroll
        for (int hh = 0; hh < 2; hh++) {
            float mx = -1e30f;
            #pragma unroll
            for (int nt = 0; nt < 16; nt++) {
                mx = fmaxf(mx, sc[mt][nt][hh*2]);
                mx = fmaxf(mx, sc[mt][nt][hh*2+1]);
            }
            mx = fmaxf(mx, __shfl_xor_sync(0xffffffffu, mx, 1));
            mx = fmaxf(mx, __shfl_xor_sync(0xffffffffu, mx, 2));
            float sum = 0.0f;
            #pragma unroll
            for (int nt = 0; nt < 16; nt++) {
                float e0 = __expf(sc[mt][nt][hh*2]   - mx);
                float e1 = __expf(sc[mt][nt][hh*2+1] - mx);
                sc[mt][nt][hh*2]   = e0;
                sc[mt][nt][hh*2+1] = e1;
                sum += e0 + e1;
            }
            sum += __shfl_xor_sync(0xffffffffu, sum, 1);
            sum += __shfl_xor_sync(0xffffffffu, sum, 2);
            inv_[mt][hh] = 1.0f / sum;
        }

    // ---- O = P V : repack S-frags as A-frags in registers ----
    float oc[2][4][4];
    #pragma unroll
    for (int mt = 0; mt < 2; mt++)
        #pragma unroll
        for (int nt = 0; nt < 4; nt++)
            #pragma unroll
            for (int v = 0; v < 4; v++) oc[mt][nt][v] = 0.0f;

    #pragma unroll
    for (int s = 0; s < 8; s++) {
        uint32_t pa[2][4];
        #pragma unroll
        for (int mt = 0; mt < 2; mt++) {
            pa[mt][0] = packh2(sc[mt][2*s][0],   sc[mt][2*s][1]);
            pa[mt][1] = packh2(sc[mt][2*s][2],   sc[mt][2*s][3]);
            pa[mt][2] = packh2(sc[mt][2*s+1][0], sc[mt][2*s+1][1]);
            pa[mt][3] = packh2(sc[mt][2*s+1][2], sc[mt][2*s+1][3]);
        }
        #pragma unroll
        for (int gg = 0; gg < 2; gg++) {
            uint32_t vb[4];
            ldsm_x4t(vb, svv + (s*16 + lrow)*QSTR + lcol + gg*16);
            #pragma unroll
            for (int mt = 0; mt < 2; mt++) {
                mma_f16(oc[mt][gg*2],     pa[mt], vb[0], vb[1]);
                mma_f16(oc[mt][gg*2 + 1], pa[mt], vb[2], vb[3]);
            }
        }
    }

    // ---- write O (normalize by row sums) ----
    #pragma unroll
    for (int mt = 0; mt < 2; mt++) {
        int i0 = wm*32 + mt*16 + (lane >> 2);
        int tok0 = stok[i0], tok1 = stok[i0 + 8];
        float in0 = inv_[mt][0], in1 = inv_[mt][1];
        #pragma unroll
        for (int nt = 0; nt < 4; nt++) {
            int col = head*HD + nt*8 + (lane & 3)*2;
            *(__half2*)(out + (size_t)tok0*CC + col) =
                __floats2half2_rn(oc[mt][nt][0]*in0, oc[mt][nt][1]*in0);
            *(__half2*)(out + (size_t)tok1*CC + col) =
                __floats2half2_rn(oc[mt][nt][2]*in1, oc[mt][nt][3]*in1);
        }
    }
}

// ---------------- host orchestration ----------------
extern "C" void kernel_launch(void* const* d_in, const int* in_sizes, int n_in,
                              void* d_out, int out_size)
{
    const float* x       = (const float*)d_in[0];
    const float* rpb1    = (const float*)d_in[1];
    const float* qkv_w1  = (const float*)d_in[2];
    const float* qkv_b1  = (const float*)d_in[3];
    const float* proj_w1 = (const float*)d_in[4];
    const float* proj_b1 = (const float*)d_in[5];
    const float* rpb2    = (const float*)d_in[6];
    const float* qkv_w2  = (const float*)d_in[7];
    const float* qkv_b2  = (const float*)d_in[8];
    const float* proj_w2 = (const float*)d_in[9];
    const float* proj_b2 = (const float*)d_in[10];
    const float* g1  = (const float*)d_in[11];
    const float* be1 = (const float*)d_in[12];
    const float* g2  = (const float*)d_in[13];
    const float* be2 = (const float*)d_in[14];
    const float* g3  = (const float*)d_in[15];
    const float* be3 = (const float*)d_in[16];
    const float* g4  = (const float*)d_in[17];
    const float* be4 = (const float*)d_in[18];
    const float* m1w1 = (const float*)d_in[19];
    const float* m1b1 = (const float*)d_in[20];
    const float* m1w2 = (const float*)d_in[21];
    const float* m1b2 = (const float*)d_in[22];
    const float* m2w1 = (const float*)d_in[23];
    const float* m2b1 = (const float*)d_in[24];
    const float* m2w2 = (const float*)d_in[25];
    const float* m2b2 = (const float*)d_in[26];
    float* out = (float*)d_out;

    __half *xnh, *qkvh, *atth, *hidh, *wh;
    float *xb;
    cudaGetSymbolAddress((void**)&xnh,  g_xnh);
    cudaGetSymbolAddress((void**)&qkvh, g_qkvh);
    cudaGetSymbolAddress((void**)&atth, g_atth);
    cudaGetSymbolAddress((void**)&hidh, g_hidh);
    cudaGetSymbolAddress((void**)&xb,   g_x);
    cudaGetSymbolAddress((void**)&wh,   g_wh);

    cudaFuncSetAttribute(hgemm_kernel<0>,
        cudaFuncAttributeMaxDynamicSharedMemorySize, GSMEM_BYTES);
    cudaFuncSetAttribute(hgemm_kernel<1>,
        cudaFuncAttributeMaxDynamicSharedMemorySize, GSMEM_BYTES);
    cudaFuncSetAttribute(hgemm_kernel<2>,
        cudaFuncAttributeMaxDynamicSharedMemorySize, GSMEM_BYTES);

    // convert weights to fp16
    cvt_kernel<<<(CC*QKV_N)/1024, 256>>>(qkv_w1,  wh + OFF_QKV1,  CC*QKV_N);
    cvt_kernel<<<(CC*CC)/1024,    256>>>(proj_w1, wh + OFF_PROJ1, CC*CC);
    cvt_kernel<<<(CC*HID)/1024,   256>>>(m1w1,    wh + OFF_M1W1,  CC*HID);
    cvt_kernel<<<(HID*CC)/1024,   256>>>(m1w2,    wh + OFF_M1W2,  HID*CC);
    cvt_kernel<<<(CC*QKV_N)/1024, 256>>>(qkv_w2,  wh + OFF_QKV2,  CC*QKV_N);
    cvt_kernel<<<(CC*CC)/1024,    256>>>(proj_w2, wh + OFF_PROJ2, CC*CC);
    cvt_kernel<<<(CC*HID)/1024,   256>>>(m2w1,    wh + OFF_M2W1,  CC*HID);
    cvt_kernel<<<(HID*CC)/1024,   256>>>(m2w2,    wh + OFF_M2W2,  HID*CC);

    const int M = NTOK;
    dim3 lnGrid(M / 8);
    dim3 attnGrid(NWIN, NHEAD);

    // ---- block 1 ----
    ln_kernel<<<lnGrid, 256>>>(x, g1, be1, xnh);
    hgemm_kernel<0><<<dim3(QKV_N/BN, M/BM), 256, GSMEM_BYTES>>>(M, QKV_N, CC, xnh, wh+OFF_QKV1, qkv_b1, nullptr, nullptr, qkvh);
    attn_kernel<false><<<attnGrid, 128>>>(qkvh, rpb1, atth);
    hgemm_kernel<2><<<dim3(CC/BN, M/BM), 256, GSMEM_BYTES>>>(M, CC, CC, atth, wh+OFF_PROJ1, proj_b1, x, xb, nullptr);
    ln_kernel<<<lnGrid, 256>>>(xb, g2, be2, xnh);
    hgemm_kernel<1><<<dim3(HID/BN, M/BM), 256, GSMEM_BYTES>>>(M, HID, CC, xnh, wh+OFF_M1W1, m1b1, nullptr, nullptr, hidh);
    hgemm_kernel<2><<<dim3(CC/BN, M/BM), 256, GSMEM_BYTES>>>(M, CC, HID, hidh, wh+OFF_M1W2, m1b2, xb, xb, nullptr);

    // ---- block 2 (shifted) ----
    ln_kernel<<<lnGrid, 256>>>(xb, g3, be3, xnh);
    hgemm_kernel<0><<<dim3(QKV_N/BN, M/BM), 256, GSMEM_BYTES>>>(M, QKV_N, CC, xnh, wh+OFF_QKV2, qkv_b2, nullptr, nullptr, qkvh);
    attn_kernel<true><<<attnGrid, 128>>>(qkvh, rpb2, atth);
    hgemm_kernel<2><<<dim3(CC/BN, M/BM), 256, GSMEM_BYTES>>>(M, CC, CC, atth, wh+OFF_PROJ2, proj_b2, xb, xb, nullptr);
    ln_kernel<<<lnGrid, 256>>>(xb, g4, be4, xnh);
    hgemm_kernel<1><<<dim3(HID/BN, M/BM), 256, GSMEM_BYTES>>>(M, HID, CC, xnh, wh+OFF_M2W1, m2b1, nullptr, nullptr, hidh);
    hgemm_kernel<2><<<dim3(CC/BN, M/BM), 256, GSMEM_BYTES>>>(M, CC, HID, hidh, wh+OFF_M2W2, m2b2, xb, out, nullptr);
}